// round 2
// baseline (speedup 1.0000x reference)
#include <cuda_runtime.h>
#include <cstdint>

#define NB   32
#define HH   56
#define WW   56
#define CIN  128
#define OUTC 128
#define GRP  8
#define GC   16
#define GC2  8
#define REL  111     // 2*56-1
#define TI   4       // i-tile per attention CTA

#define BNSCALE 0.9995003746876562f   // 1/sqrt(1 + 1e-3)

// ---- scratch (static device arrays; no allocation) ----
__device__ float g_qs[(size_t)NB * GRP * HH * WW * GC2];   // [b][g][i][w][c8]
__device__ float g_ks[(size_t)NB * GRP * HH * WW * GC2];   // [b][g][j][w][c8]
__device__ float g_vs[(size_t)NB * GRP * HH * WW * GC];    // [b][g][j][w][c16]

// ============================================================
// Kernel 1: fused QKV projection + BN, scatter to group layout
// GEMM: M=100352 rows (b,h,w), K=128, N=256 (q64|k64|v128)
// ============================================================
__global__ __launch_bounds__(256) void proj_kernel(
    const float* __restrict__ x,
    const float* __restrict__ wq, const float* __restrict__ wk, const float* __restrict__ wv,
    const float* __restrict__ gq, const float* __restrict__ bq,
    const float* __restrict__ gk, const float* __restrict__ bk,
    const float* __restrict__ gv, const float* __restrict__ bv)
{
    extern __shared__ float smem[];
    float* xs = smem;                 // [64][129]
    float* ws = smem + 64 * 129;      // [128][64]

    const int cb = blockIdx.x;        // 0..3 column tile (q, k, v-lo, v-hi)
    const int rb = blockIdx.y;        // 0..1567 row tile
    const int t  = threadIdx.x;
    const int row0 = rb * 64;

    // load x tile [64][128] (padded rows of 129)
    {
        const int k4 = (t & 31) * 4;
        const int rb8 = t >> 5;
        #pragma unroll
        for (int p = 0; p < 8; p++) {
            const int r = rb8 + p * 8;
            float4 v = *(const float4*)(x + (size_t)(row0 + r) * CIN + k4);
            float* dst = xs + r * 129 + k4;
            dst[0] = v.x; dst[1] = v.y; dst[2] = v.z; dst[3] = v.w;
        }
    }
    // load weight tile [128][64]
    {
        const float* wsrc; int ld, co;
        if (cb == 0)      { wsrc = wq; ld = 64;  co = 0;  }
        else if (cb == 1) { wsrc = wk; ld = 64;  co = 0;  }
        else if (cb == 2) { wsrc = wv; ld = 128; co = 0;  }
        else              { wsrc = wv; ld = 128; co = 64; }
        const int c4 = (t & 15) * 4;
        const int kb = t >> 4;
        #pragma unroll
        for (int p = 0; p < 8; p++) {
            const int kk = kb + p * 16;
            float4 v = *(const float4*)(wsrc + (size_t)kk * ld + co + c4);
            *(float4*)(ws + kk * 64 + c4) = v;
        }
    }
    __syncthreads();

    const int ty = t >> 4, tx = t & 15;
    float acc[4][4];
    #pragma unroll
    for (int a = 0; a < 4; a++)
        #pragma unroll
        for (int bq_ = 0; bq_ < 4; bq_++) acc[a][bq_] = 0.f;

    #pragma unroll 4
    for (int kk = 0; kk < 128; kk++) {
        float a0 = xs[(ty * 4 + 0) * 129 + kk];
        float a1 = xs[(ty * 4 + 1) * 129 + kk];
        float a2 = xs[(ty * 4 + 2) * 129 + kk];
        float a3 = xs[(ty * 4 + 3) * 129 + kk];
        float4 bb = *(float4*)(ws + kk * 64 + tx * 4);
        acc[0][0] = fmaf(a0, bb.x, acc[0][0]); acc[0][1] = fmaf(a0, bb.y, acc[0][1]);
        acc[0][2] = fmaf(a0, bb.z, acc[0][2]); acc[0][3] = fmaf(a0, bb.w, acc[0][3]);
        acc[1][0] = fmaf(a1, bb.x, acc[1][0]); acc[1][1] = fmaf(a1, bb.y, acc[1][1]);
        acc[1][2] = fmaf(a1, bb.z, acc[1][2]); acc[1][3] = fmaf(a1, bb.w, acc[1][3]);
        acc[2][0] = fmaf(a2, bb.x, acc[2][0]); acc[2][1] = fmaf(a2, bb.y, acc[2][1]);
        acc[2][2] = fmaf(a2, bb.z, acc[2][2]); acc[2][3] = fmaf(a2, bb.w, acc[2][3]);
        acc[3][0] = fmaf(a3, bb.x, acc[3][0]); acc[3][1] = fmaf(a3, bb.y, acc[3][1]);
        acc[3][2] = fmaf(a3, bb.z, acc[3][2]); acc[3][3] = fmaf(a3, bb.w, acc[3][3]);
    }

    // epilogue: BN + scatter into grouped layouts
    if (cb <= 1) {
        float* dst = (cb == 0) ? g_qs : g_ks;
        const float* gg = (cb == 0) ? gq : gk;
        const float* bbv = (cb == 0) ? bq : bk;
        #pragma unroll
        for (int ii = 0; ii < 4; ii++) {
            const int row = row0 + ty * 4 + ii;
            const int b = row / (HH * WW);
            const int rem = row - b * (HH * WW);
            const int h = rem / WW, w = rem - (rem / WW) * WW;
            #pragma unroll
            for (int jj = 0; jj < 4; jj++) {
                const int ch = tx * 4 + jj;               // 0..63
                const float sc = gg[ch] * BNSCALE, be = bbv[ch];
                const int gi = ch >> 3, c = ch & 7;
                dst[((((size_t)b * GRP + gi) * HH + h) * WW + w) * GC2 + c] =
                    fmaf(acc[ii][jj], sc, be);
            }
        }
    } else {
        #pragma unroll
        for (int ii = 0; ii < 4; ii++) {
            const int row = row0 + ty * 4 + ii;
            const int b = row / (HH * WW);
            const int rem = row - b * (HH * WW);
            const int h = rem / WW, w = rem - (rem / WW) * WW;
            #pragma unroll
            for (int jj = 0; jj < 4; jj++) {
                const int cv = (cb - 2) * 64 + tx * 4 + jj;   // 0..127
                const float sc = gv[cv] * BNSCALE, be = bv[cv];
                const int gi = cv >> 4, c = cv & 15;
                g_vs[((((size_t)b * GRP + gi) * HH + h) * WW + w) * GC + c] =
                    fmaf(acc[ii][jj], sc, be);
            }
        }
    }
}

// ============================================================
// Kernel 2: fused attention (logits + softmax-over-w + sv/sve + out BN)
// grid: (14 i-tiles, 8 groups, 32 batch), 256 threads, thread=(w, ti)
// ============================================================
__global__ __launch_bounds__(256) void attn_kernel(
    const float* __restrict__ qrel, const float* __restrict__ krel, const float* __restrict__ vrel,
    const float* __restrict__ gqk, const float* __restrict__ bqk,
    const float* __restrict__ gqr, const float* __restrict__ bqr,
    const float* __restrict__ gkr, const float* __restrict__ bkr,
    const float* __restrict__ gsv, const float* __restrict__ bsv,
    const float* __restrict__ gsve, const float* __restrict__ bsve,
    float* __restrict__ out)
{
    __shared__ __align__(16) float q_s[TI * WW * GC2];       // 1792
    __shared__ __align__(16) float kbuf[2][WW * GC2];         // 2*448
    __shared__ __align__(16) float vbuf[2][WW * GC];          // 2*896
    __shared__ __align__(16) float Ls[TI][WW + 1];
    __shared__ __align__(16) float Ps[TI][WW + 1];
    __shared__ __align__(16) float qrel_s[REL * GC2];
    __shared__ __align__(16) float krel_s[REL * GC2];
    __shared__ __align__(16) float vrel_s[REL * GC];

    const int it = blockIdx.x, g = blockIdx.y, b = blockIdx.z;
    const int t = threadIdx.x;
    const int w = t >> 2, ti = t & 3;
    const bool active = (w < WW);
    const int i = it * TI + ti;
    const int lane = t & 31, wid = t >> 5;

    const size_t bgrow = ((size_t)b * GRP + g) * HH;          // base row index (j/i units)

    // cooperative loads (rel tables, q tile, j=0 buffers)
    for (int idx = t; idx < REL * GC2; idx += 256) { qrel_s[idx] = qrel[idx]; krel_s[idx] = krel[idx]; }
    for (int idx = t; idx < REL * GC;  idx += 256) vrel_s[idx] = vrel[idx];
    {
        const float* qsrc = g_qs + (bgrow + it * TI) * (WW * GC2);
        for (int idx = t; idx < TI * WW * GC2; idx += 256) q_s[idx] = qsrc[idx];
        const float* ksrc = g_ks + bgrow * (WW * GC2);
        const float* vsrc = g_vs + bgrow * (WW * GC);
        for (int idx = t; idx < WW * GC2; idx += 256) kbuf[0][idx] = ksrc[idx];
        for (int idx = t; idx < WW * GC;  idx += 256) vbuf[0][idx] = vsrc[idx];
    }
    __syncthreads();

    const float sqk = gqk[g] * BNSCALE, Bqk = bqk[g];
    const float sqr = gqr[g] * BNSCALE, Bqr = bqr[g];
    const float skr = gkr[g] * BNSCALE, Bkr = bkr[g];

    float qv[8];
    if (active) {
        const float* qp = q_s + (ti * WW + w) * GC2;
        float4 a = *(const float4*)qp;
        float4 c = *(const float4*)(qp + 4);
        qv[0] = a.x; qv[1] = a.y; qv[2] = a.z; qv[3] = a.w;
        qv[4] = c.x; qv[5] = c.y; qv[6] = c.z; qv[7] = c.w;
    }

    float sv[GC], sve[GC];
    #pragma unroll
    for (int c = 0; c < GC; c++) { sv[c] = 0.f; sve[c] = 0.f; }

    for (int j = 0; j < HH; j++) {
        const int cur = j & 1, nxt = cur ^ 1;

        // stage next-j K/V rows into registers (latency overlapped with compute)
        float sk0 = 0.f, sk1 = 0.f, sv0 = 0.f, sv1 = 0.f, sv2 = 0.f, sv3 = 0.f;
        if (j + 1 < HH) {
            const float* ksrc = g_ks + (bgrow + j + 1) * (WW * GC2);
            const float* vsrc = g_vs + (bgrow + j + 1) * (WW * GC);
            sk0 = ksrc[t];
            if (t < 192) sk1 = ksrc[t + 256];
            sv0 = vsrc[t];
            sv1 = vsrc[t + 256];
            sv2 = vsrc[t + 512];
            if (t < 128) sv3 = vsrc[t + 768];
        }

        // logits
        if (active) {
            const float* kp = kbuf[cur] + w * GC2;
            float4 k0 = *(const float4*)kp;
            float4 k1 = *(const float4*)(kp + 4);
            float kq[8] = {k0.x, k0.y, k0.z, k0.w, k1.x, k1.y, k1.z, k1.w};
            const int rq = i - j + (HH - 1);
            const int rk = j - i + (HH - 1);
            const float* qe = qrel_s + rq * GC2;
            const float* ke = krel_s + rk * GC2;
            float dqk = 0.f, dqr = 0.f, dkr = 0.f;
            #pragma unroll
            for (int c = 0; c < 8; c++) {
                dqk = fmaf(qv[c], kq[c], dqk);
                dqr = fmaf(qv[c], qe[c], dqr);
                dkr = fmaf(kq[c], ke[c], dkr);
            }
            Ls[ti][w] = fmaf(dqk, sqk, Bqk) + fmaf(dqr, sqr, Bqr) + fmaf(dkr, skr, Bkr);
        }
        __syncthreads();

        // softmax over w (per ti row); warps 0..3 each own a row
        if (wid < TI) {
            float v0 = Ls[wid][lane];
            const int l2 = lane + 32;
            float v1 = (l2 < WW) ? Ls[wid][l2] : -1e30f;
            float m = fmaxf(v0, v1);
            #pragma unroll
            for (int o = 16; o; o >>= 1) m = fmaxf(m, __shfl_xor_sync(0xffffffffu, m, o));
            float e0 = __expf(v0 - m);
            float e1 = (l2 < WW) ? __expf(v1 - m) : 0.f;
            float s = e0 + e1;
            #pragma unroll
            for (int o = 16; o; o >>= 1) s += __shfl_xor_sync(0xffffffffu, s, o);
            const float inv = __fdividef(1.f, s);
            Ps[wid][lane] = e0 * inv;
            if (l2 < WW) Ps[wid][l2] = e1 * inv;
        }
        __syncthreads();

        // accumulate sv / sve
        if (active) {
            const float P = Ps[ti][w];
            const float* vp = vbuf[cur] + w * GC;
            const float* ve = vrel_s + (j - i + (HH - 1)) * GC;
            float4 va0 = *(const float4*)(vp + 0), va1 = *(const float4*)(vp + 4);
            float4 va2 = *(const float4*)(vp + 8), va3 = *(const float4*)(vp + 12);
            float4 ea0 = *(const float4*)(ve + 0), ea1 = *(const float4*)(ve + 4);
            float4 ea2 = *(const float4*)(ve + 8), ea3 = *(const float4*)(ve + 12);
            sv[0]  = fmaf(P, va0.x, sv[0]);  sv[1]  = fmaf(P, va0.y, sv[1]);
            sv[2]  = fmaf(P, va0.z, sv[2]);  sv[3]  = fmaf(P, va0.w, sv[3]);
            sv[4]  = fmaf(P, va1.x, sv[4]);  sv[5]  = fmaf(P, va1.y, sv[5]);
            sv[6]  = fmaf(P, va1.z, sv[6]);  sv[7]  = fmaf(P, va1.w, sv[7]);
            sv[8]  = fmaf(P, va2.x, sv[8]);  sv[9]  = fmaf(P, va2.y, sv[9]);
            sv[10] = fmaf(P, va2.z, sv[10]); sv[11] = fmaf(P, va2.w, sv[11]);
            sv[12] = fmaf(P, va3.x, sv[12]); sv[13] = fmaf(P, va3.y, sv[13]);
            sv[14] = fmaf(P, va3.z, sv[14]); sv[15] = fmaf(P, va3.w, sv[15]);
            sve[0]  = fmaf(P, ea0.x, sve[0]);  sve[1]  = fmaf(P, ea0.y, sve[1]);
            sve[2]  = fmaf(P, ea0.z, sve[2]);  sve[3]  = fmaf(P, ea0.w, sve[3]);
            sve[4]  = fmaf(P, ea1.x, sve[4]);  sve[5]  = fmaf(P, ea1.y, sve[5]);
            sve[6]  = fmaf(P, ea1.z, sve[6]);  sve[7]  = fmaf(P, ea1.w, sve[7]);
            sve[8]  = fmaf(P, ea2.x, sve[8]);  sve[9]  = fmaf(P, ea2.y, sve[9]);
            sve[10] = fmaf(P, ea2.z, sve[10]); sve[11] = fmaf(P, ea2.w, sve[11]);
            sve[12] = fmaf(P, ea3.x, sve[12]); sve[13] = fmaf(P, ea3.y, sve[13]);
            sve[14] = fmaf(P, ea3.z, sve[14]); sve[15] = fmaf(P, ea3.w, sve[15]);
        }

        // commit staged next-j rows
        if (j + 1 < HH) {
            kbuf[nxt][t] = sk0;
            if (t < 192) kbuf[nxt][t + 256] = sk1;
            vbuf[nxt][t] = sv0;
            vbuf[nxt][t + 256] = sv1;
            vbuf[nxt][t + 512] = sv2;
            if (t < 128) vbuf[nxt][t + 768] = sv3;
        }
        __syncthreads();
    }

    // epilogue: output BN and store
    if (active) {
        const int ch0 = g * GC;
        const size_t ob = (((size_t)b * HH + i) * WW + w) * OUTC + ch0;
        #pragma unroll
        for (int c = 0; c < GC; c++) {
            const int ch = ch0 + c;
            out[ob + c] = fmaf(sv[c], gsv[ch] * BNSCALE, bsv[ch])
                        + fmaf(sve[c], gsve[ch] * BNSCALE, bsve[ch]);
        }
    }
}

// ============================================================
extern "C" void kernel_launch(void* const* d_in, const int* in_sizes, int n_in,
                              void* d_out, int out_size)
{
    const float* x    = (const float*)d_in[0];
    const float* w_q  = (const float*)d_in[1];
    const float* w_k  = (const float*)d_in[2];
    const float* w_v  = (const float*)d_in[3];
    const float* q_rel = (const float*)d_in[4];
    const float* k_rel = (const float*)d_in[5];
    const float* v_rel = (const float*)d_in[6];
    const float* g_q  = (const float*)d_in[7];
    const float* b_q  = (const float*)d_in[8];
    const float* g_k  = (const float*)d_in[9];
    const float* b_k  = (const float*)d_in[10];
    const float* g_v  = (const float*)d_in[11];
    const float* b_v  = (const float*)d_in[12];
    const float* g_qk = (const float*)d_in[13];
    const float* b_qk = (const float*)d_in[14];
    const float* g_qr = (const float*)d_in[15];
    const float* b_qr = (const float*)d_in[16];
    const float* g_kr = (const float*)d_in[17];
    const float* b_kr = (const float*)d_in[18];
    const float* g_sv = (const float*)d_in[19];
    const float* b_sv = (const float*)d_in[20];
    const float* g_sve = (const float*)d_in[21];
    const float* b_sve = (const float*)d_in[22];

    const int proj_smem = (64 * 129 + 128 * 64) * sizeof(float);  // 65792 B
    cudaFuncSetAttribute(proj_kernel, cudaFuncAttributeMaxDynamicSharedMemorySize, proj_smem);

    dim3 g1(4, (NB * HH * WW) / 64);   // (4, 1568)
    proj_kernel<<<g1, 256, proj_smem>>>(x, w_q, w_k, w_v,
                                        g_q, b_q, g_k, b_k, g_v, b_v);

    dim3 g2(HH / TI, GRP, NB);         // (14, 8, 32)
    attn_kernel<<<g2, 256>>>(q_rel, k_rel, v_rel,
                             g_qk, b_qk, g_qr, b_qr, g_kr, b_kr,
                             g_sv, b_sv, g_sve, b_sve,
                             (float*)d_out);
}

// round 3
// speedup vs baseline: 1.8496x; 1.8496x over previous
#include <cuda_runtime.h>
#include <cstdint>

#define NB   32
#define HH   56
#define WW   56
#define CIN  128
#define OUTC 128
#define GRP  8
#define GC   16
#define GC2  8
#define REL  111     // 2*56-1
#define WARPS 8      // i-rows per attention CTA (one per warp)

#define BNSCALE 0.9995003746876562f   // 1/sqrt(1 + 1e-3)

// ---- scratch (static device arrays; no allocation) ----
__device__ float g_qs[(size_t)NB * GRP * HH * WW * GC2];   // [b][g][i][w][c8]
__device__ float g_ks[(size_t)NB * GRP * HH * WW * GC2];   // [b][g][j][w][c8]
__device__ float g_vs[(size_t)NB * GRP * HH * WW * GC];    // [b][g][j][w][c16]

// ============================================================
// Kernel 1: fused QKV projection + BN, scatter to group layout
// ============================================================
__global__ __launch_bounds__(256) void proj_kernel(
    const float* __restrict__ x,
    const float* __restrict__ wq, const float* __restrict__ wk, const float* __restrict__ wv,
    const float* __restrict__ gq, const float* __restrict__ bq,
    const float* __restrict__ gk, const float* __restrict__ bk,
    const float* __restrict__ gv, const float* __restrict__ bv)
{
    extern __shared__ float smem[];
    float* xs = smem;                 // [64][129]
    float* ws = smem + 64 * 129;      // [128][64]

    const int cb = blockIdx.x;        // 0..3 (q, k, v-lo, v-hi)
    const int rb = blockIdx.y;
    const int t  = threadIdx.x;
    const int row0 = rb * 64;

    {
        const int k4 = (t & 31) * 4;
        const int rb8 = t >> 5;
        #pragma unroll
        for (int p = 0; p < 8; p++) {
            const int r = rb8 + p * 8;
            float4 v = *(const float4*)(x + (size_t)(row0 + r) * CIN + k4);
            float* dst = xs + r * 129 + k4;
            dst[0] = v.x; dst[1] = v.y; dst[2] = v.z; dst[3] = v.w;
        }
    }
    {
        const float* wsrc; int ld, co;
        if (cb == 0)      { wsrc = wq; ld = 64;  co = 0;  }
        else if (cb == 1) { wsrc = wk; ld = 64;  co = 0;  }
        else if (cb == 2) { wsrc = wv; ld = 128; co = 0;  }
        else              { wsrc = wv; ld = 128; co = 64; }
        const int c4 = (t & 15) * 4;
        const int kb = t >> 4;
        #pragma unroll
        for (int p = 0; p < 8; p++) {
            const int kk = kb + p * 16;
            float4 v = *(const float4*)(wsrc + (size_t)kk * ld + co + c4);
            *(float4*)(ws + kk * 64 + c4) = v;
        }
    }
    __syncthreads();

    const int ty = t >> 4, tx = t & 15;
    float acc[4][4];
    #pragma unroll
    for (int a = 0; a < 4; a++)
        #pragma unroll
        for (int b2 = 0; b2 < 4; b2++) acc[a][b2] = 0.f;

    #pragma unroll 4
    for (int kk = 0; kk < 128; kk++) {
        float a0 = xs[(ty * 4 + 0) * 129 + kk];
        float a1 = xs[(ty * 4 + 1) * 129 + kk];
        float a2 = xs[(ty * 4 + 2) * 129 + kk];
        float a3 = xs[(ty * 4 + 3) * 129 + kk];
        float4 bb = *(float4*)(ws + kk * 64 + tx * 4);
        acc[0][0] = fmaf(a0, bb.x, acc[0][0]); acc[0][1] = fmaf(a0, bb.y, acc[0][1]);
        acc[0][2] = fmaf(a0, bb.z, acc[0][2]); acc[0][3] = fmaf(a0, bb.w, acc[0][3]);
        acc[1][0] = fmaf(a1, bb.x, acc[1][0]); acc[1][1] = fmaf(a1, bb.y, acc[1][1]);
        acc[1][2] = fmaf(a1, bb.z, acc[1][2]); acc[1][3] = fmaf(a1, bb.w, acc[1][3]);
        acc[2][0] = fmaf(a2, bb.x, acc[2][0]); acc[2][1] = fmaf(a2, bb.y, acc[2][1]);
        acc[2][2] = fmaf(a2, bb.z, acc[2][2]); acc[2][3] = fmaf(a2, bb.w, acc[2][3]);
        acc[3][0] = fmaf(a3, bb.x, acc[3][0]); acc[3][1] = fmaf(a3, bb.y, acc[3][1]);
        acc[3][2] = fmaf(a3, bb.z, acc[3][2]); acc[3][3] = fmaf(a3, bb.w, acc[3][3]);
    }

    if (cb <= 1) {
        float* dst = (cb == 0) ? g_qs : g_ks;
        const float* gg = (cb == 0) ? gq : gk;
        const float* bbv = (cb == 0) ? bq : bk;
        #pragma unroll
        for (int ii = 0; ii < 4; ii++) {
            const int row = row0 + ty * 4 + ii;
            const int b = row / (HH * WW);
            const int rem = row - b * (HH * WW);
            const int h = rem / WW, w = rem - (rem / WW) * WW;
            #pragma unroll
            for (int jj = 0; jj < 4; jj++) {
                const int ch = tx * 4 + jj;
                const float sc = gg[ch] * BNSCALE, be = bbv[ch];
                const int gi = ch >> 3, c = ch & 7;
                dst[((((size_t)b * GRP + gi) * HH + h) * WW + w) * GC2 + c] =
                    fmaf(acc[ii][jj], sc, be);
            }
        }
    } else {
        #pragma unroll
        for (int ii = 0; ii < 4; ii++) {
            const int row = row0 + ty * 4 + ii;
            const int b = row / (HH * WW);
            const int rem = row - b * (HH * WW);
            const int h = rem / WW, w = rem - (rem / WW) * WW;
            #pragma unroll
            for (int jj = 0; jj < 4; jj++) {
                const int cv = (cb - 2) * 64 + tx * 4 + jj;
                const float sc = gv[cv] * BNSCALE, be = bv[cv];
                const int gi = cv >> 4, c = cv & 15;
                g_vs[((((size_t)b * GRP + gi) * HH + h) * WW + w) * GC + c] =
                    fmaf(acc[ii][jj], sc, be);
            }
        }
    }
}

// ============================================================
// Kernel 2: fused attention, warp-local softmax.
// grid (7 i-tiles, 8 g, 32 b); 8 warps/CTA, warp owns one i-row;
// lane owns w = {lane, lane+32}. One __syncthreads per j (buffer swap).
// ============================================================
__global__ __launch_bounds__(256, 2) void attn_kernel(
    const float* __restrict__ qrel, const float* __restrict__ krel, const float* __restrict__ vrel,
    const float* __restrict__ gqk,
    const float* __restrict__ gqr,
    const float* __restrict__ gkr,
    const float* __restrict__ gsv, const float* __restrict__ bsv,
    const float* __restrict__ gsve, const float* __restrict__ bsve,
    float* __restrict__ out)
{
    __shared__ __align__(16) float kbuf[2][64 * GC2];     // padded to w=64
    __shared__ __align__(16) float vbuf[2][64 * GC];
    __shared__ __align__(16) float qrel_s[REL * GC2];     // scaled by gqr/gqk
    __shared__ __align__(16) float krel_s[REL * GC2];     // scaled by gkr*BNSCALE
    __shared__ __align__(16) float vrel_s[REL * GC];

    const int it = blockIdx.x, g = blockIdx.y, b = blockIdx.z;
    const int t = threadIdx.x, lane = t & 31, wid = t >> 5;
    const int i = it * WARPS + wid;
    const size_t bgrow = ((size_t)b * GRP + g) * HH;

    const float sqk = gqk[g] * BNSCALE;
    const float fqr = gqr[g] / gqk[g];    // (sqr/sqk); BNSCALE cancels
    const float skr = gkr[g] * BNSCALE;

    // cooperative loads; fold scales into rel tables (biases cancel in softmax)
    for (int idx = t; idx < REL * GC2; idx += 256) {
        qrel_s[idx] = qrel[idx] * fqr;
        krel_s[idx] = krel[idx] * skr;
    }
    for (int idx = t; idx < REL * GC; idx += 256) vrel_s[idx] = vrel[idx];
    // zero pads (w in [56,64))
    if (t < 64)  { kbuf[0][448 + t] = 0.f; kbuf[1][448 + t] = 0.f; }
    if (t < 128) { vbuf[0][896 + t] = 0.f; vbuf[1][896 + t] = 0.f; }
    // j = 0 rows
    {
        const float* ksrc = g_ks + bgrow * (WW * GC2);
        const float* vsrc = g_vs + bgrow * (WW * GC);
        for (int idx = t; idx < WW * GC2; idx += 256) kbuf[0][idx] = ksrc[idx];
        for (int idx = t; idx < WW * GC;  idx += 256) vbuf[0][idx] = vsrc[idx];
    }

    // q registers for both w slots, pre-scaled by sqk
    float qv0[8], qv1[8];
    {
        const float* qrow = g_qs + (bgrow + i) * (WW * GC2);
        float4 a = *(const float4*)(qrow + lane * GC2);
        float4 c = *(const float4*)(qrow + lane * GC2 + 4);
        qv0[0] = a.x * sqk; qv0[1] = a.y * sqk; qv0[2] = a.z * sqk; qv0[3] = a.w * sqk;
        qv0[4] = c.x * sqk; qv0[5] = c.y * sqk; qv0[6] = c.z * sqk; qv0[7] = c.w * sqk;
        if (lane < WW - 32) {
            float4 a1 = *(const float4*)(qrow + (lane + 32) * GC2);
            float4 c1 = *(const float4*)(qrow + (lane + 32) * GC2 + 4);
            qv1[0] = a1.x * sqk; qv1[1] = a1.y * sqk; qv1[2] = a1.z * sqk; qv1[3] = a1.w * sqk;
            qv1[4] = c1.x * sqk; qv1[5] = c1.y * sqk; qv1[6] = c1.z * sqk; qv1[7] = c1.w * sqk;
        } else {
            #pragma unroll
            for (int c2 = 0; c2 < 8; c2++) qv1[c2] = 0.f;
        }
    }
    __syncthreads();

    float sv0[GC], sv1[GC], sve0[GC], sve1[GC];
    #pragma unroll
    for (int c = 0; c < GC; c++) { sv0[c] = 0.f; sv1[c] = 0.f; sve0[c] = 0.f; sve1[c] = 0.f; }

    const bool w1ok = (lane < WW - 32);

    for (int j = 0; j < HH; j++) {
        const int cur = j & 1, nxt = cur ^ 1;

        // stage next-j K/V rows into registers
        float stk0 = 0.f, stk1 = 0.f, stv0 = 0.f, stv1 = 0.f, stv2 = 0.f, stv3 = 0.f;
        if (j + 1 < HH) {
            const float* ksrc = g_ks + (bgrow + j + 1) * (WW * GC2);
            const float* vsrc = g_vs + (bgrow + j + 1) * (WW * GC);
            stk0 = ksrc[t];
            if (t < 192) stk1 = ksrc[t + 256];
            stv0 = vsrc[t];
            stv1 = vsrc[t + 256];
            stv2 = vsrc[t + 512];
            if (t < 128) stv3 = vsrc[t + 768];
        }

        // ---- logits (both w slots) ----
        float k0[8], k1[8], qe[8], ke[8];
        {
            const float* kp = kbuf[cur] + lane * GC2;
            float4 x0 = *(const float4*)kp;
            float4 x1 = *(const float4*)(kp + 4);
            k0[0]=x0.x; k0[1]=x0.y; k0[2]=x0.z; k0[3]=x0.w;
            k0[4]=x1.x; k0[5]=x1.y; k0[6]=x1.z; k0[7]=x1.w;
            const float* kp1 = kbuf[cur] + (lane + 32) * GC2;   // padded, safe
            float4 y0 = *(const float4*)kp1;
            float4 y1 = *(const float4*)(kp1 + 4);
            k1[0]=y0.x; k1[1]=y0.y; k1[2]=y0.z; k1[3]=y0.w;
            k1[4]=y1.x; k1[5]=y1.y; k1[6]=y1.z; k1[7]=y1.w;
            const float* qep = qrel_s + (i - j + HH - 1) * GC2;  // warp-uniform
            const float* kep = krel_s + (j - i + HH - 1) * GC2;
            float4 q0 = *(const float4*)qep, q1 = *(const float4*)(qep + 4);
            float4 e0 = *(const float4*)kep, e1 = *(const float4*)(kep + 4);
            qe[0]=q0.x; qe[1]=q0.y; qe[2]=q0.z; qe[3]=q0.w;
            qe[4]=q1.x; qe[5]=q1.y; qe[6]=q1.z; qe[7]=q1.w;
            ke[0]=e0.x; ke[1]=e0.y; ke[2]=e0.z; ke[3]=e0.w;
            ke[4]=e1.x; ke[5]=e1.y; ke[6]=e1.z; ke[7]=e1.w;
        }
        float L0 = 0.f, L1 = 0.f;
        #pragma unroll
        for (int c = 0; c < 8; c++) {
            L0 = fmaf(qv0[c], k0[c] + qe[c], L0);
            L0 = fmaf(k0[c], ke[c], L0);
            L1 = fmaf(qv1[c], k1[c] + qe[c], L1);
            L1 = fmaf(k1[c], ke[c], L1);
        }

        // ---- warp-local softmax over w ----
        float m = fmaxf(L0, w1ok ? L1 : -1e30f);
        #pragma unroll
        for (int o = 16; o; o >>= 1) m = fmaxf(m, __shfl_xor_sync(0xffffffffu, m, o));
        float e0 = __expf(L0 - m);
        float e1 = w1ok ? __expf(L1 - m) : 0.f;
        float s = e0 + e1;
        #pragma unroll
        for (int o = 16; o; o >>= 1) s += __shfl_xor_sync(0xffffffffu, s, o);
        const float inv = __fdividef(1.f, s);
        const float P0 = e0 * inv, P1 = e1 * inv;

        // ---- accumulate sv / sve ----
        {
            const float* vp0 = vbuf[cur] + lane * GC;
            const float* vp1 = vbuf[cur] + (lane + 32) * GC;    // padded (zeros), P1=0 there
            const float* vep = vrel_s + (j - i + HH - 1) * GC;  // warp-uniform
            #pragma unroll
            for (int q4 = 0; q4 < 4; q4++) {
                float4 a = *(const float4*)(vp0 + q4 * 4);
                float4 bq = *(const float4*)(vp1 + q4 * 4);
                float4 e = *(const float4*)(vep + q4 * 4);
                sv0[q4*4+0] = fmaf(P0, a.x, sv0[q4*4+0]);
                sv0[q4*4+1] = fmaf(P0, a.y, sv0[q4*4+1]);
                sv0[q4*4+2] = fmaf(P0, a.z, sv0[q4*4+2]);
                sv0[q4*4+3] = fmaf(P0, a.w, sv0[q4*4+3]);
                sv1[q4*4+0] = fmaf(P1, bq.x, sv1[q4*4+0]);
                sv1[q4*4+1] = fmaf(P1, bq.y, sv1[q4*4+1]);
                sv1[q4*4+2] = fmaf(P1, bq.z, sv1[q4*4+2]);
                sv1[q4*4+3] = fmaf(P1, bq.w, sv1[q4*4+3]);
                sve0[q4*4+0] = fmaf(P0, e.x, sve0[q4*4+0]);
                sve0[q4*4+1] = fmaf(P0, e.y, sve0[q4*4+1]);
                sve0[q4*4+2] = fmaf(P0, e.z, sve0[q4*4+2]);
                sve0[q4*4+3] = fmaf(P0, e.w, sve0[q4*4+3]);
                sve1[q4*4+0] = fmaf(P1, e.x, sve1[q4*4+0]);
                sve1[q4*4+1] = fmaf(P1, e.y, sve1[q4*4+1]);
                sve1[q4*4+2] = fmaf(P1, e.z, sve1[q4*4+2]);
                sve1[q4*4+3] = fmaf(P1, e.w, sve1[q4*4+3]);
            }
        }

        // commit staged rows to next buffer
        if (j + 1 < HH) {
            kbuf[nxt][t] = stk0;
            if (t < 192) kbuf[nxt][t + 256] = stk1;
            vbuf[nxt][t] = stv0;
            vbuf[nxt][t + 256] = stv1;
            vbuf[nxt][t + 512] = stv2;
            if (t < 128) vbuf[nxt][t + 768] = stv3;
        }
        __syncthreads();
    }

    // ---- epilogue: output BN + store ----
    {
        const int ch0 = g * GC;
        const size_t rowbase = (((size_t)b * HH + i) * WW) * OUTC + ch0;
        float o0[GC], o1[GC];
        #pragma unroll
        for (int c = 0; c < GC; c++) {
            const float s1 = __ldg(gsv + ch0 + c) * BNSCALE;
            const float b1 = __ldg(bsv + ch0 + c);
            const float s2 = __ldg(gsve + ch0 + c) * BNSCALE;
            const float b2 = __ldg(bsve + ch0 + c);
            o0[c] = fmaf(sv0[c], s1, b1) + fmaf(sve0[c], s2, b2);
            o1[c] = fmaf(sv1[c], s1, b1) + fmaf(sve1[c], s2, b2);
        }
        float* dst0 = out + rowbase + (size_t)lane * OUTC;
        #pragma unroll
        for (int q4 = 0; q4 < 4; q4++)
            *(float4*)(dst0 + q4 * 4) = make_float4(o0[q4*4], o0[q4*4+1], o0[q4*4+2], o0[q4*4+3]);
        if (w1ok) {
            float* dst1 = out + rowbase + (size_t)(lane + 32) * OUTC;
            #pragma unroll
            for (int q4 = 0; q4 < 4; q4++)
                *(float4*)(dst1 + q4 * 4) = make_float4(o1[q4*4], o1[q4*4+1], o1[q4*4+2], o1[q4*4+3]);
        }
    }
}

// ============================================================
extern "C" void kernel_launch(void* const* d_in, const int* in_sizes, int n_in,
                              void* d_out, int out_size)
{
    const float* x    = (const float*)d_in[0];
    const float* w_q  = (const float*)d_in[1];
    const float* w_k  = (const float*)d_in[2];
    const float* w_v  = (const float*)d_in[3];
    const float* q_rel = (const float*)d_in[4];
    const float* k_rel = (const float*)d_in[5];
    const float* v_rel = (const float*)d_in[6];
    const float* g_q  = (const float*)d_in[7];
    const float* b_q  = (const float*)d_in[8];
    const float* g_k  = (const float*)d_in[9];
    const float* b_k  = (const float*)d_in[10];
    const float* g_v  = (const float*)d_in[11];
    const float* b_v  = (const float*)d_in[12];
    const float* g_qk = (const float*)d_in[13];
    const float* g_qr = (const float*)d_in[15];
    const float* g_kr = (const float*)d_in[17];
    const float* g_sv = (const float*)d_in[19];
    const float* b_sv = (const float*)d_in[20];
    const float* g_sve = (const float*)d_in[21];
    const float* b_sve = (const float*)d_in[22];

    const int proj_smem = (64 * 129 + 128 * 64) * sizeof(float);
    cudaFuncSetAttribute(proj_kernel, cudaFuncAttributeMaxDynamicSharedMemorySize, proj_smem);

    dim3 g1(4, (NB * HH * WW) / 64);
    proj_kernel<<<g1, 256, proj_smem>>>(x, w_q, w_k, w_v,
                                        g_q, b_q, g_k, b_k, g_v, b_v);

    dim3 g2(HH / WARPS, GRP, NB);      // (7, 8, 32)
    attn_kernel<<<g2, 256>>>(q_rel, k_rel, v_rel,
                             g_qk, g_qr, g_kr,
                             g_sv, b_sv, g_sve, b_sve,
                             (float*)d_out);
}

// round 7
// speedup vs baseline: 2.7220x; 1.4717x over previous
#include <cuda_runtime.h>
#include <cstdint>

#define NB   32
#define HH   56
#define WW   56
#define CIN  128
#define OUTC 128
#define GRP  8
#define GC   16
#define GC2  8
#define REL  111     // 2*56-1
#define WARPS 8      // i-rows per attention CTA (one per warp)
#define KS   12      // padded K row stride (words) — conflict-free LDS.128
#define VS   20      // padded V row stride (words) — conflict-free LDS.128

#define BNSCALE 0.9995003746876562f   // 1/sqrt(1 + 1e-3)

// ---- scratch (static device arrays; no allocation) ----
__device__ float g_qs[(size_t)NB * GRP * HH * WW * GC2];   // [b][g][i][w][c8]
__device__ float g_ks[(size_t)NB * GRP * HH * WW * GC2];   // [b][g][j][w][c8]
__device__ float g_vs[(size_t)NB * GRP * HH * WW * GC];    // [b][g][j][w][c16]

// ============================================================
// Kernel 1: fused QKV projection + BN, scatter to group layout
// ============================================================
__global__ __launch_bounds__(256) void proj_kernel(
    const float* __restrict__ x,
    const float* __restrict__ wq, const float* __restrict__ wk, const float* __restrict__ wv,
    const float* __restrict__ gq, const float* __restrict__ bq,
    const float* __restrict__ gk, const float* __restrict__ bk,
    const float* __restrict__ gv, const float* __restrict__ bv)
{
    extern __shared__ float smem[];
    float* xs = smem;                 // [64][129]
    float* ws = smem + 64 * 129;      // [128][64]

    const int cb = blockIdx.x;        // 0..3 (q, k, v-lo, v-hi)
    const int rb = blockIdx.y;
    const int t  = threadIdx.x;
    const int row0 = rb * 64;

    {
        const int k4 = (t & 31) * 4;
        const int rb8 = t >> 5;
        #pragma unroll
        for (int p = 0; p < 8; p++) {
            const int r = rb8 + p * 8;
            float4 v = *(const float4*)(x + (size_t)(row0 + r) * CIN + k4);
            float* dst = xs + r * 129 + k4;
            dst[0] = v.x; dst[1] = v.y; dst[2] = v.z; dst[3] = v.w;
        }
    }
    {
        const float* wsrc; int ld, co;
        if (cb == 0)      { wsrc = wq; ld = 64;  co = 0;  }
        else if (cb == 1) { wsrc = wk; ld = 64;  co = 0;  }
        else if (cb == 2) { wsrc = wv; ld = 128; co = 0;  }
        else              { wsrc = wv; ld = 128; co = 64; }
        const int c4 = (t & 15) * 4;
        const int kb = t >> 4;
        #pragma unroll
        for (int p = 0; p < 8; p++) {
            const int kk = kb + p * 16;
            float4 v = *(const float4*)(wsrc + (size_t)kk * ld + co + c4);
            *(float4*)(ws + kk * 64 + c4) = v;
        }
    }
    __syncthreads();

    const int ty = t >> 4, tx = t & 15;
    float acc[4][4];
    #pragma unroll
    for (int a = 0; a < 4; a++)
        #pragma unroll
        for (int b2 = 0; b2 < 4; b2++) acc[a][b2] = 0.f;

    #pragma unroll 4
    for (int kk = 0; kk < 128; kk++) {
        float a0 = xs[(ty * 4 + 0) * 129 + kk];
        float a1 = xs[(ty * 4 + 1) * 129 + kk];
        float a2 = xs[(ty * 4 + 2) * 129 + kk];
        float a3 = xs[(ty * 4 + 3) * 129 + kk];
        float4 bb = *(float4*)(ws + kk * 64 + tx * 4);
        acc[0][0] = fmaf(a0, bb.x, acc[0][0]); acc[0][1] = fmaf(a0, bb.y, acc[0][1]);
        acc[0][2] = fmaf(a0, bb.z, acc[0][2]); acc[0][3] = fmaf(a0, bb.w, acc[0][3]);
        acc[1][0] = fmaf(a1, bb.x, acc[1][0]); acc[1][1] = fmaf(a1, bb.y, acc[1][1]);
        acc[1][2] = fmaf(a1, bb.z, acc[1][2]); acc[1][3] = fmaf(a1, bb.w, acc[1][3]);
        acc[2][0] = fmaf(a2, bb.x, acc[2][0]); acc[2][1] = fmaf(a2, bb.y, acc[2][1]);
        acc[2][2] = fmaf(a2, bb.z, acc[2][2]); acc[2][3] = fmaf(a2, bb.w, acc[2][3]);
        acc[3][0] = fmaf(a3, bb.x, acc[3][0]); acc[3][1] = fmaf(a3, bb.y, acc[3][1]);
        acc[3][2] = fmaf(a3, bb.z, acc[3][2]); acc[3][3] = fmaf(a3, bb.w, acc[3][3]);
    }

    if (cb <= 1) {
        float* dst = (cb == 0) ? g_qs : g_ks;
        const float* gg = (cb == 0) ? gq : gk;
        const float* bbv = (cb == 0) ? bq : bk;
        #pragma unroll
        for (int ii = 0; ii < 4; ii++) {
            const int row = row0 + ty * 4 + ii;
            const int b = row / (HH * WW);
            const int rem = row - b * (HH * WW);
            const int h = rem / WW, w = rem - (rem / WW) * WW;
            #pragma unroll
            for (int jj = 0; jj < 4; jj++) {
                const int ch = tx * 4 + jj;
                const float sc = gg[ch] * BNSCALE, be = bbv[ch];
                const int gi = ch >> 3, c = ch & 7;
                dst[((((size_t)b * GRP + gi) * HH + h) * WW + w) * GC2 + c] =
                    fmaf(acc[ii][jj], sc, be);
            }
        }
    } else {
        #pragma unroll
        for (int ii = 0; ii < 4; ii++) {
            const int row = row0 + ty * 4 + ii;
            const int b = row / (HH * WW);
            const int rem = row - b * (HH * WW);
            const int h = rem / WW, w = rem - (rem / WW) * WW;
            #pragma unroll
            for (int jj = 0; jj < 4; jj++) {
                const int cv = (cb - 2) * 64 + tx * 4 + jj;
                const float sc = gv[cv] * BNSCALE, be = bv[cv];
                const int gi = cv >> 4, c = cv & 15;
                g_vs[((((size_t)b * GRP + gi) * HH + h) * WW + w) * GC + c] =
                    fmaf(acc[ii][jj], sc, be);
            }
        }
    }
}

// ============================================================
// Kernel 2: fused attention, warp-local softmax, padded smem
// (conflict-free LDS.128). grid (7, 8, 32); warp owns one i-row.
// ============================================================
__global__ __launch_bounds__(256, 2) void attn_kernel(
    const float* __restrict__ qrel, const float* __restrict__ krel, const float* __restrict__ vrel,
    const float* __restrict__ gqk,
    const float* __restrict__ gqr,
    const float* __restrict__ gkr,
    const float* __restrict__ gsv, const float* __restrict__ bsv,
    const float* __restrict__ gsve, const float* __restrict__ bsve,
    float* __restrict__ out)
{
    __shared__ __align__(16) float kbuf[2][64 * KS];      // padded rows (w=64, stride 12)
    __shared__ __align__(16) float vbuf[2][64 * VS];      // padded rows (w=64, stride 20)
    __shared__ __align__(16) float qrel_s[REL * GC2];     // scaled by gqr/gqk
    __shared__ __align__(16) float krel_s[REL * GC2];     // scaled by gkr*BNSCALE
    __shared__ __align__(16) float vrel_s[REL * GC];

    const int it = blockIdx.x, g = blockIdx.y, b = blockIdx.z;
    const int t = threadIdx.x, lane = t & 31, wid = t >> 5;
    const int i = it * WARPS + wid;
    const size_t bgrow = ((size_t)b * GRP + g) * HH;

    const float sqk = gqk[g] * BNSCALE;
    const float fqr = gqr[g] / gqk[g];    // (sqr/sqk); BNSCALE cancels
    const float skr = gkr[g] * BNSCALE;

    // cooperative loads; fold scales into rel tables (biases cancel in softmax)
    for (int idx = t; idx < REL * GC2; idx += 256) {
        qrel_s[idx] = qrel[idx] * fqr;
        krel_s[idx] = krel[idx] * skr;
    }
    for (int idx = t; idx < REL * GC; idx += 256) vrel_s[idx] = vrel[idx];

    // zero pad rows (w in [56,64)) — read by lanes 24..31's dead slot (P1=0)
    if (t < 64)  {
        const int w = 56 + (t >> 3), c = t & 7;
        kbuf[0][w * KS + c] = 0.f; kbuf[1][w * KS + c] = 0.f;
    }
    if (t < 128) {
        const int w = 56 + (t >> 4), c = t & 15;
        vbuf[0][w * VS + c] = 0.f; vbuf[1][w * VS + c] = 0.f;
    }
    // j = 0 rows (float4 granularity into padded layout)
    {
        const float4* k4 = (const float4*)(g_ks + bgrow * (WW * GC2));
        const float4* v4 = (const float4*)(g_vs + bgrow * (WW * GC));
        if (t < 112) {
            const int w = t >> 1, c = (t & 1) * 4;
            *(float4*)&kbuf[0][w * KS + c] = k4[t];
        }
        if (t < 224) {
            const int w = t >> 2, c = (t & 3) * 4;
            *(float4*)&vbuf[0][w * VS + c] = v4[t];
        }
    }

    // q registers for both w slots, pre-scaled by sqk
    float qv0[8], qv1[8];
    {
        const float* qrow = g_qs + (bgrow + i) * (WW * GC2);
        float4 a = *(const float4*)(qrow + lane * GC2);
        float4 c = *(const float4*)(qrow + lane * GC2 + 4);
        qv0[0] = a.x * sqk; qv0[1] = a.y * sqk; qv0[2] = a.z * sqk; qv0[3] = a.w * sqk;
        qv0[4] = c.x * sqk; qv0[5] = c.y * sqk; qv0[6] = c.z * sqk; qv0[7] = c.w * sqk;
        if (lane < WW - 32) {
            float4 a1 = *(const float4*)(qrow + (lane + 32) * GC2);
            float4 c1 = *(const float4*)(qrow + (lane + 32) * GC2 + 4);
            qv1[0] = a1.x * sqk; qv1[1] = a1.y * sqk; qv1[2] = a1.z * sqk; qv1[3] = a1.w * sqk;
            qv1[4] = c1.x * sqk; qv1[5] = c1.y * sqk; qv1[6] = c1.z * sqk; qv1[7] = c1.w * sqk;
        } else {
            #pragma unroll
            for (int c2 = 0; c2 < 8; c2++) qv1[c2] = 0.f;
        }
    }
    __syncthreads();

    float sv0[GC], sv1[GC], sve0[GC], sve1[GC];
    #pragma unroll
    for (int c = 0; c < GC; c++) { sv0[c] = 0.f; sv1[c] = 0.f; sve0[c] = 0.f; sve1[c] = 0.f; }

    const bool w1ok = (lane < WW - 32);

    for (int j = 0; j < HH; j++) {
        const int cur = j & 1, nxt = cur ^ 1;

        // stage next-j K/V rows into registers (float4, 112/224 threads)
        float4 stk = make_float4(0.f, 0.f, 0.f, 0.f);
        float4 stv = make_float4(0.f, 0.f, 0.f, 0.f);
        if (j + 1 < HH) {
            const float4* k4 = (const float4*)(g_ks + (bgrow + j + 1) * (WW * GC2));
            const float4* v4 = (const float4*)(g_vs + (bgrow + j + 1) * (WW * GC));
            if (t < 112) stk = k4[t];
            if (t < 224) stv = v4[t];
        }

        // ---- logits (both w slots) ----
        float k0[8], k1[8], qe[8], ke[8];
        {
            const float* kp = kbuf[cur] + lane * KS;
            float4 x0 = *(const float4*)kp;
            float4 x1 = *(const float4*)(kp + 4);
            k0[0]=x0.x; k0[1]=x0.y; k0[2]=x0.z; k0[3]=x0.w;
            k0[4]=x1.x; k0[5]=x1.y; k0[6]=x1.z; k0[7]=x1.w;
            const float* kp1 = kbuf[cur] + (lane + 32) * KS;    // padded, zeros beyond 56
            float4 y0 = *(const float4*)kp1;
            float4 y1 = *(const float4*)(kp1 + 4);
            k1[0]=y0.x; k1[1]=y0.y; k1[2]=y0.z; k1[3]=y0.w;
            k1[4]=y1.x; k1[5]=y1.y; k1[6]=y1.z; k1[7]=y1.w;
            const float* qep = qrel_s + (i - j + HH - 1) * GC2;  // warp-uniform broadcast
            const float* kep = krel_s + (j - i + HH - 1) * GC2;
            float4 q0 = *(const float4*)qep, q1 = *(const float4*)(qep + 4);
            float4 e0 = *(const float4*)kep, e1 = *(const float4*)(kep + 4);
            qe[0]=q0.x; qe[1]=q0.y; qe[2]=q0.z; qe[3]=q0.w;
            qe[4]=q1.x; qe[5]=q1.y; qe[6]=q1.z; qe[7]=q1.w;
            ke[0]=e0.x; ke[1]=e0.y; ke[2]=e0.z; ke[3]=e0.w;
            ke[4]=e1.x; ke[5]=e1.y; ke[6]=e1.z; ke[7]=e1.w;
        }
        float L0 = 0.f, L1 = 0.f;
        #pragma unroll
        for (int c = 0; c < 8; c++) {
            L0 = fmaf(qv0[c], k0[c] + qe[c], L0);
            L0 = fmaf(k0[c], ke[c], L0);
            L1 = fmaf(qv1[c], k1[c] + qe[c], L1);
            L1 = fmaf(k1[c], ke[c], L1);
        }

        // ---- warp-local softmax over w ----
        float m = fmaxf(L0, w1ok ? L1 : -1e30f);
        #pragma unroll
        for (int o = 16; o; o >>= 1) m = fmaxf(m, __shfl_xor_sync(0xffffffffu, m, o));
        float e0 = __expf(L0 - m);
        float e1 = w1ok ? __expf(L1 - m) : 0.f;
        float s = e0 + e1;
        #pragma unroll
        for (int o = 16; o; o >>= 1) s += __shfl_xor_sync(0xffffffffu, s, o);
        const float inv = __fdividef(1.f, s);
        const float P0 = e0 * inv, P1 = e1 * inv;

        // ---- accumulate sv / sve ----
        {
            const float* vp0 = vbuf[cur] + lane * VS;
            const float* vp1 = vbuf[cur] + (lane + 32) * VS;    // padded zeros, P1=0 there
            const float* vep = vrel_s + (j - i + HH - 1) * GC;  // warp-uniform broadcast
            #pragma unroll
            for (int q4 = 0; q4 < 4; q4++) {
                float4 a = *(const float4*)(vp0 + q4 * 4);
                float4 bq = *(const float4*)(vp1 + q4 * 4);
                float4 e = *(const float4*)(vep + q4 * 4);
                sv0[q4*4+0] = fmaf(P0, a.x, sv0[q4*4+0]);
                sv0[q4*4+1] = fmaf(P0, a.y, sv0[q4*4+1]);
                sv0[q4*4+2] = fmaf(P0, a.z, sv0[q4*4+2]);
                sv0[q4*4+3] = fmaf(P0, a.w, sv0[q4*4+3]);
                sv1[q4*4+0] = fmaf(P1, bq.x, sv1[q4*4+0]);
                sv1[q4*4+1] = fmaf(P1, bq.y, sv1[q4*4+1]);
                sv1[q4*4+2] = fmaf(P1, bq.z, sv1[q4*4+2]);
                sv1[q4*4+3] = fmaf(P1, bq.w, sv1[q4*4+3]);
                sve0[q4*4+0] = fmaf(P0, e.x, sve0[q4*4+0]);
                sve0[q4*4+1] = fmaf(P0, e.y, sve0[q4*4+1]);
                sve0[q4*4+2] = fmaf(P0, e.z, sve0[q4*4+2]);
                sve0[q4*4+3] = fmaf(P0, e.w, sve0[q4*4+3]);
                sve1[q4*4+0] = fmaf(P1, e.x, sve1[q4*4+0]);
                sve1[q4*4+1] = fmaf(P1, e.y, sve1[q4*4+1]);
                sve1[q4*4+2] = fmaf(P1, e.z, sve1[q4*4+2]);
                sve1[q4*4+3] = fmaf(P1, e.w, sve1[q4*4+3]);
            }
        }

        // commit staged rows to next buffer (padded layout)
        if (j + 1 < HH) {
            if (t < 112) {
                const int w = t >> 1, c = (t & 1) * 4;
                *(float4*)&kbuf[nxt][w * KS + c] = stk;
            }
            if (t < 224) {
                const int w = t >> 2, c = (t & 3) * 4;
                *(float4*)&vbuf[nxt][w * VS + c] = stv;
            }
        }
        __syncthreads();
    }

    // ---- epilogue: output BN + store ----
    {
        const int ch0 = g * GC;
        const size_t rowbase = (((size_t)b * HH + i) * WW) * OUTC + ch0;
        float o0[GC], o1[GC];
        #pragma unroll
        for (int c = 0; c < GC; c++) {
            const float s1 = __ldg(gsv + ch0 + c) * BNSCALE;
            const float b1 = __ldg(bsv + ch0 + c);
            const float s2 = __ldg(gsve + ch0 + c) * BNSCALE;
            const float b2 = __ldg(bsve + ch0 + c);
            o0[c] = fmaf(sv0[c], s1, b1) + fmaf(sve0[c], s2, b2);
            o1[c] = fmaf(sv1[c], s1, b1) + fmaf(sve1[c], s2, b2);
        }
        float* dst0 = out + rowbase + (size_t)lane * OUTC;
        #pragma unroll
        for (int q4 = 0; q4 < 4; q4++)
            *(float4*)(dst0 + q4 * 4) = make_float4(o0[q4*4], o0[q4*4+1], o0[q4*4+2], o0[q4*4+3]);
        if (w1ok) {
            float* dst1 = out + rowbase + (size_t)(lane + 32) * OUTC;
            #pragma unroll
            for (int q4 = 0; q4 < 4; q4++)
                *(float4*)(dst1 + q4 * 4) = make_float4(o1[q4*4], o1[q4*4+1], o1[q4*4+2], o1[q4*4+3]);
        }
    }
}

// ============================================================
extern "C" void kernel_launch(void* const* d_in, const int* in_sizes, int n_in,
                              void* d_out, int out_size)
{
    const float* x    = (const float*)d_in[0];
    const float* w_q  = (const float*)d_in[1];
    const float* w_k  = (const float*)d_in[2];
    const float* w_v  = (const float*)d_in[3];
    const float* q_rel = (const float*)d_in[4];
    const float* k_rel = (const float*)d_in[5];
    const float* v_rel = (const float*)d_in[6];
    const float* g_q  = (const float*)d_in[7];
    const float* b_q  = (const float*)d_in[8];
    const float* g_k  = (const float*)d_in[9];
    const float* b_k  = (const float*)d_in[10];
    const float* g_v  = (const float*)d_in[11];
    const float* b_v  = (const float*)d_in[12];
    const float* g_qk = (const float*)d_in[13];
    const float* g_qr = (const float*)d_in[15];
    const float* g_kr = (const float*)d_in[17];
    const float* g_sv = (const float*)d_in[19];
    const float* b_sv = (const float*)d_in[20];
    const float* g_sve = (const float*)d_in[21];
    const float* b_sve = (const float*)d_in[22];

    const int proj_smem = (64 * 129 + 128 * 64) * sizeof(float);
    cudaFuncSetAttribute(proj_kernel, cudaFuncAttributeMaxDynamicSharedMemorySize, proj_smem);

    dim3 g1(4, (NB * HH * WW) / 64);
    proj_kernel<<<g1, 256, proj_smem>>>(x, w_q, w_k, w_v,
                                        g_q, b_q, g_k, b_k, g_v, b_v);

    dim3 g2(HH / WARPS, GRP, NB);      // (7, 8, 32)
    attn_kernel<<<g2, 256>>>(q_rel, k_rel, v_rel,
                             g_qk, g_qr, g_kr,
                             g_sv, b_sv, g_sve, b_sve,
                             (float*)d_out);
}

// round 11
// speedup vs baseline: 3.1770x; 1.1672x over previous
#include <cuda_runtime.h>
#include <cstdint>

#define NB   32
#define HH   56
#define WW   56
#define CIN  128
#define OUTC 128
#define GRP  8
#define GC   16
#define GC2  8
#define REL  111     // 2*56-1
#define KS   12      // padded K row stride (words) — conflict-free LDS.128
#define VS   20      // padded V row stride (words) — conflict-free LDS.128

#define BNSCALE 0.9995003746876562f   // 1/sqrt(1 + 1e-3)

typedef unsigned long long u64;

// ---- packed f32x2 helpers (FFMA2 path, sm_103a) ----
__device__ __forceinline__ u64 pack2(float lo, float hi) {
    u64 d; asm("mov.b64 %0, {%1, %2};" : "=l"(d) : "f"(lo), "f"(hi)); return d;
}
__device__ __forceinline__ float lo2(u64 v) {
    float f; asm("{\n\t.reg .f32 h;\n\tmov.b64 {%0, h}, %1;\n\t}" : "=f"(f) : "l"(v)); return f;
}
__device__ __forceinline__ float hi2(u64 v) {
    float f; asm("{\n\t.reg .f32 l;\n\tmov.b64 {l, %0}, %1;\n\t}" : "=f"(f) : "l"(v)); return f;
}
__device__ __forceinline__ u64 ffma2(u64 a, u64 b, u64 c) {
    u64 d; asm("fma.rn.f32x2 %0, %1, %2, %3;" : "=l"(d) : "l"(a), "l"(b), "l"(c)); return d;
}
__device__ __forceinline__ u64 fadd2(u64 a, u64 b) {
    u64 d; asm("add.rn.f32x2 %0, %1, %2;" : "=l"(d) : "l"(a), "l"(b)); return d;
}
__device__ __forceinline__ u64 fmul2(u64 a, u64 b) {
    u64 d; asm("mul.rn.f32x2 %0, %1, %2;" : "=l"(d) : "l"(a), "l"(b)); return d;
}
__device__ __forceinline__ void ld4(u64 dst[4], const float* p) {
    ulonglong2 a = *(const ulonglong2*)p;
    ulonglong2 b = *(const ulonglong2*)(p + 4);
    dst[0] = a.x; dst[1] = a.y; dst[2] = b.x; dst[3] = b.y;
}
__device__ __forceinline__ void ld8(u64 dst[8], const float* p) {
    ld4(dst, p); ld4(dst + 4, p + 8);
}

// ---- scratch (static device arrays; no allocation) ----
__device__ __align__(16) float g_qs[(size_t)NB * GRP * HH * WW * GC2];   // [b][g][i][w][c8]
__device__ __align__(16) float g_ks[(size_t)NB * GRP * HH * WW * GC2];   // [b][g][j][w][c8]
__device__ __align__(16) float g_vs[(size_t)NB * GRP * HH * WW * GC];    // [b][g][j][w][c16]

// ============================================================
// Kernel 1: fused QKV projection + BN (FFMA2 inner loop)
// ============================================================
__global__ __launch_bounds__(256) void proj_kernel(
    const float* __restrict__ x,
    const float* __restrict__ wq, const float* __restrict__ wk, const float* __restrict__ wv,
    const float* __restrict__ gq, const float* __restrict__ bq,
    const float* __restrict__ gk, const float* __restrict__ bk,
    const float* __restrict__ gv, const float* __restrict__ bv)
{
    extern __shared__ float smem[];
    float* xs = smem;                 // [64][129]
    float* ws = smem + 64 * 129;      // [128][64]

    const int cb = blockIdx.x;        // 0..3 (q, k, v-lo, v-hi)
    const int rb = blockIdx.y;
    const int t  = threadIdx.x;
    const int row0 = rb * 64;

    {
        const int k4 = (t & 31) * 4;
        const int rb8 = t >> 5;
        #pragma unroll
        for (int p = 0; p < 8; p++) {
            const int r = rb8 + p * 8;
            float4 v = *(const float4*)(x + (size_t)(row0 + r) * CIN + k4);
            float* dst = xs + r * 129 + k4;
            dst[0] = v.x; dst[1] = v.y; dst[2] = v.z; dst[3] = v.w;
        }
    }
    {
        const float* wsrc; int ld, co;
        if (cb == 0)      { wsrc = wq; ld = 64;  co = 0;  }
        else if (cb == 1) { wsrc = wk; ld = 64;  co = 0;  }
        else if (cb == 2) { wsrc = wv; ld = 128; co = 0;  }
        else              { wsrc = wv; ld = 128; co = 64; }
        const int c4 = (t & 15) * 4;
        const int kb = t >> 4;
        #pragma unroll
        for (int p = 0; p < 8; p++) {
            const int kk = kb + p * 16;
            float4 v = *(const float4*)(wsrc + (size_t)kk * ld + co + c4);
            *(float4*)(ws + kk * 64 + c4) = v;
        }
    }
    __syncthreads();

    const int ty = t >> 4, tx = t & 15;
    u64 acc2[4][2];
    #pragma unroll
    for (int a = 0; a < 4; a++) { acc2[a][0] = 0ull; acc2[a][1] = 0ull; }

    #pragma unroll 4
    for (int kk = 0; kk < 128; kk++) {
        float a0 = xs[(ty * 4 + 0) * 129 + kk];
        float a1 = xs[(ty * 4 + 1) * 129 + kk];
        float a2 = xs[(ty * 4 + 2) * 129 + kk];
        float a3 = xs[(ty * 4 + 3) * 129 + kk];
        ulonglong2 bb = *(const ulonglong2*)(ws + kk * 64 + tx * 4);
        u64 p0 = pack2(a0, a0), p1 = pack2(a1, a1);
        u64 p2 = pack2(a2, a2), p3 = pack2(a3, a3);
        acc2[0][0] = ffma2(p0, bb.x, acc2[0][0]); acc2[0][1] = ffma2(p0, bb.y, acc2[0][1]);
        acc2[1][0] = ffma2(p1, bb.x, acc2[1][0]); acc2[1][1] = ffma2(p1, bb.y, acc2[1][1]);
        acc2[2][0] = ffma2(p2, bb.x, acc2[2][0]); acc2[2][1] = ffma2(p2, bb.y, acc2[2][1]);
        acc2[3][0] = ffma2(p3, bb.x, acc2[3][0]); acc2[3][1] = ffma2(p3, bb.y, acc2[3][1]);
    }

    float acc[4][4];
    #pragma unroll
    for (int a = 0; a < 4; a++) {
        acc[a][0] = lo2(acc2[a][0]); acc[a][1] = hi2(acc2[a][0]);
        acc[a][2] = lo2(acc2[a][1]); acc[a][3] = hi2(acc2[a][1]);
    }

    if (cb <= 1) {
        float* dst = (cb == 0) ? g_qs : g_ks;
        const float* gg = (cb == 0) ? gq : gk;
        const float* bbv = (cb == 0) ? bq : bk;
        #pragma unroll
        for (int ii = 0; ii < 4; ii++) {
            const int row = row0 + ty * 4 + ii;
            const int b = row / (HH * WW);
            const int rem = row - b * (HH * WW);
            const int h = rem / WW, w = rem - (rem / WW) * WW;
            #pragma unroll
            for (int jj = 0; jj < 4; jj++) {
                const int ch = tx * 4 + jj;
                const float sc = gg[ch] * BNSCALE, be = bbv[ch];
                const int gi = ch >> 3, c = ch & 7;
                dst[((((size_t)b * GRP + gi) * HH + h) * WW + w) * GC2 + c] =
                    fmaf(acc[ii][jj], sc, be);
            }
        }
    } else {
        #pragma unroll
        for (int ii = 0; ii < 4; ii++) {
            const int row = row0 + ty * 4 + ii;
            const int b = row / (HH * WW);
            const int rem = row - b * (HH * WW);
            const int h = rem / WW, w = rem - (rem / WW) * WW;
            #pragma unroll
            for (int jj = 0; jj < 4; jj++) {
                const int cv = (cb - 2) * 64 + tx * 4 + jj;
                const float sc = gv[cv] * BNSCALE, be = bv[cv];
                const int gi = cv >> 4, c = cv & 15;
                g_vs[((((size_t)b * GRP + gi) * HH + h) * WW + w) * GC + c] =
                    fmaf(acc[ii][jj], sc, be);
            }
        }
    }
}

// ============================================================
// Kernel 2: fused attention. 128 threads = 4 warps; each warp
// owns TWO i-rows (shares K/V smem reads between them); packed
// f32x2 math; merged sv/sve accumulators (scales pre-folded).
// grid (7, 8, 32).
// ============================================================
__device__ __forceinline__ float logit8(const u64 qv[4], const u64 k[4],
                                        const u64 qe[4], const u64 ke[4]) {
    u64 s = fmul2(k[0], ke[0]);
    s = ffma2(k[1], ke[1], s);
    s = ffma2(k[2], ke[2], s);
    s = ffma2(k[3], ke[3], s);
    s = ffma2(qv[0], fadd2(k[0], qe[0]), s);
    s = ffma2(qv[1], fadd2(k[1], qe[1]), s);
    s = ffma2(qv[2], fadd2(k[2], qe[2]), s);
    s = ffma2(qv[3], fadd2(k[3], qe[3]), s);
    return lo2(s) + hi2(s);
}

__device__ __forceinline__ void softmax2(float L0, float L1, bool ok,
                                         float& P0, float& P1) {
    float m = fmaxf(L0, ok ? L1 : -1e30f);
    #pragma unroll
    for (int o = 16; o; o >>= 1) m = fmaxf(m, __shfl_xor_sync(0xffffffffu, m, o));
    float e0 = __expf(L0 - m);
    float e1 = ok ? __expf(L1 - m) : 0.f;
    float s = e0 + e1;
    #pragma unroll
    for (int o = 16; o; o >>= 1) s += __shfl_xor_sync(0xffffffffu, s, o);
    const float inv = __fdividef(1.f, s);
    P0 = e0 * inv; P1 = e1 * inv;
}

__global__ __launch_bounds__(128, 3) void attn_kernel(
    const float* __restrict__ qrel, const float* __restrict__ krel, const float* __restrict__ vrel,
    const float* __restrict__ gqk,
    const float* __restrict__ gqr,
    const float* __restrict__ gkr,
    const float* __restrict__ gsv, const float* __restrict__ bsv,
    const float* __restrict__ gsve, const float* __restrict__ bsve,
    float* __restrict__ out)
{
    __shared__ __align__(16) float kbuf[2][64 * KS];
    __shared__ __align__(16) float vbuf[2][64 * VS];     // pre-scaled by gsv
    __shared__ __align__(16) float qrel_s[REL * GC2];    // * gqr/gqk
    __shared__ __align__(16) float krel_s[REL * GC2];    // * gkr*BNSCALE
    __shared__ __align__(16) float vrel_s[REL * GC];     // * gsve*BNSCALE

    const int it = blockIdx.x, g = blockIdx.y, b = blockIdx.z;
    const int t = threadIdx.x, lane = t & 31, wid = t >> 5;
    const int iA = it * 8 + wid * 2, iB = iA + 1;
    const size_t bgrow = ((size_t)b * GRP + g) * HH;
    const int ch0 = g * GC;

    const float sqk = gqk[g] * BNSCALE;
    const float fqr = gqr[g] / gqk[g];
    const float skr = gkr[g] * BNSCALE;

    for (int idx = t; idx < REL * GC2; idx += 128) {
        qrel_s[idx] = qrel[idx] * fqr;
        krel_s[idx] = krel[idx] * skr;
    }
    {   // vrel scaled by gsve (c = idx&15 constant per thread under stride 128)
        const float s2 = __ldg(gsve + ch0 + (t & 15)) * BNSCALE;
        for (int idx = t; idx < REL * GC; idx += 128) vrel_s[idx] = vrel[idx] * s2;
    }

    // zero pad rows (w in [56,64))
    if (t < 64) {
        const int w = 56 + (t >> 3), c = t & 7;
        kbuf[0][w * KS + c] = 0.f; kbuf[1][w * KS + c] = 0.f;
    }
    {
        const int w = 56 + (t >> 4), c = t & 15;
        vbuf[0][w * VS + c] = 0.f; vbuf[1][w * VS + c] = 0.f;
    }

    // per-thread V staging scale pairs (c4 = (t&3)*4, invariant under +128)
    const int c4 = (t & 3) * 4;
    const u64 s1p0 = pack2(__ldg(gsv + ch0 + c4 + 0) * BNSCALE,
                           __ldg(gsv + ch0 + c4 + 1) * BNSCALE);
    const u64 s1p1 = pack2(__ldg(gsv + ch0 + c4 + 2) * BNSCALE,
                           __ldg(gsv + ch0 + c4 + 3) * BNSCALE);

    // j = 0 fill
    {
        const ulonglong2* k2 = (const ulonglong2*)(g_ks + bgrow * (WW * GC2));
        const ulonglong2* v2 = (const ulonglong2*)(g_vs + bgrow * (WW * GC));
        if (t < 112) *(ulonglong2*)&kbuf[0][(t >> 1) * KS + (t & 1) * 4] = k2[t];
        ulonglong2 sv = v2[t];
        sv.x = fmul2(sv.x, s1p0); sv.y = fmul2(sv.y, s1p1);
        *(ulonglong2*)&vbuf[0][(t >> 2) * VS + c4] = sv;
        if (t < 96) {
            ulonglong2 sw = v2[t + 128];
            sw.x = fmul2(sw.x, s1p0); sw.y = fmul2(sw.y, s1p1);
            *(ulonglong2*)&vbuf[0][((t + 128) >> 2) * VS + c4] = sw;
        }
    }

    // q registers (both i-rows, both w slots), pre-scaled by sqk
    const bool w1ok = (lane < WW - 32);
    const u64 sqk2 = pack2(sqk, sqk);
    u64 qvA0[4], qvA1[4], qvB0[4], qvB1[4];
    {
        const float* qrA = g_qs + (bgrow + iA) * (WW * GC2);
        const float* qrB = g_qs + (bgrow + iB) * (WW * GC2);
        u64 tmp[4];
        ld4(tmp, qrA + lane * GC2);
        #pragma unroll
        for (int p = 0; p < 4; p++) qvA0[p] = fmul2(tmp[p], sqk2);
        ld4(tmp, qrB + lane * GC2);
        #pragma unroll
        for (int p = 0; p < 4; p++) qvB0[p] = fmul2(tmp[p], sqk2);
        if (w1ok) {
            ld4(tmp, qrA + (lane + 32) * GC2);
            #pragma unroll
            for (int p = 0; p < 4; p++) qvA1[p] = fmul2(tmp[p], sqk2);
            ld4(tmp, qrB + (lane + 32) * GC2);
            #pragma unroll
            for (int p = 0; p < 4; p++) qvB1[p] = fmul2(tmp[p], sqk2);
        } else {
            #pragma unroll
            for (int p = 0; p < 4; p++) { qvA1[p] = 0ull; qvB1[p] = 0ull; }
        }
    }
    __syncthreads();

    u64 accA0[8], accA1[8], accB0[8], accB1[8];
    #pragma unroll
    for (int p = 0; p < 8; p++) { accA0[p] = 0ull; accA1[p] = 0ull; accB0[p] = 0ull; accB1[p] = 0ull; }

    for (int j = 0; j < HH; j++) {
        const int cur = j & 1, nxt = cur ^ 1;

        // stage next-j K/V rows (V pre-scaled by gsv)
        ulonglong2 stk, stv0, stv1;
        if (j + 1 < HH) {
            const ulonglong2* k2 = (const ulonglong2*)(g_ks + (bgrow + j + 1) * (WW * GC2));
            const ulonglong2* v2 = (const ulonglong2*)(g_vs + (bgrow + j + 1) * (WW * GC));
            if (t < 112) stk = k2[t];
            stv0 = v2[t];
            if (t < 96) stv1 = v2[t + 128];
        }

        // ---- logits (2 i-rows × 2 slots), K regs shared ----
        u64 k0[4], k1[4];
        ld4(k0, kbuf[cur] + lane * KS);
        ld4(k1, kbuf[cur] + (lane + 32) * KS);

        u64 qeA[4], keA[4], qeB[4], keB[4];
        ld4(qeA, qrel_s + (iA - j + HH - 1) * GC2);
        ld4(keA, krel_s + (j - iA + HH - 1) * GC2);
        ld4(qeB, qrel_s + (iB - j + HH - 1) * GC2);
        ld4(keB, krel_s + (j - iB + HH - 1) * GC2);

        const float LA0 = logit8(qvA0, k0, qeA, keA);
        const float LA1 = logit8(qvA1, k1, qeA, keA);
        const float LB0 = logit8(qvB0, k0, qeB, keB);
        const float LB1 = logit8(qvB1, k1, qeB, keB);

        // ---- warp-local softmax (independent per i-row) ----
        float PA0, PA1, PB0, PB1;
        softmax2(LA0, LA1, w1ok, PA0, PA1);
        softmax2(LB0, LB1, w1ok, PB0, PB1);

        // ---- merged accumulation: acc += P * (V*s1 + ve*s2) ----
        {
            u64 v0[8], v1[8];
            ld8(v0, vbuf[cur] + lane * VS);
            ld8(v1, vbuf[cur] + (lane + 32) * VS);

            u64 veA[8];
            ld8(veA, vrel_s + (j - iA + HH - 1) * GC);
            const u64 pA0 = pack2(PA0, PA0), pA1 = pack2(PA1, PA1);
            #pragma unroll
            for (int p = 0; p < 8; p++) {
                accA0[p] = ffma2(pA0, fadd2(v0[p], veA[p]), accA0[p]);
                accA1[p] = ffma2(pA1, fadd2(v1[p], veA[p]), accA1[p]);
            }
            u64 veB[8];
            ld8(veB, vrel_s + (j - iB + HH - 1) * GC);
            const u64 pB0 = pack2(PB0, PB0), pB1 = pack2(PB1, PB1);
            #pragma unroll
            for (int p = 0; p < 8; p++) {
                accB0[p] = ffma2(pB0, fadd2(v0[p], veB[p]), accB0[p]);
                accB1[p] = ffma2(pB1, fadd2(v1[p], veB[p]), accB1[p]);
            }
        }

        // commit staged rows
        if (j + 1 < HH) {
            if (t < 112) *(ulonglong2*)&kbuf[nxt][(t >> 1) * KS + (t & 1) * 4] = stk;
            stv0.x = fmul2(stv0.x, s1p0); stv0.y = fmul2(stv0.y, s1p1);
            *(ulonglong2*)&vbuf[nxt][(t >> 2) * VS + c4] = stv0;
            if (t < 96) {
                stv1.x = fmul2(stv1.x, s1p0); stv1.y = fmul2(stv1.y, s1p1);
                *(ulonglong2*)&vbuf[nxt][((t + 128) >> 2) * VS + c4] = stv1;
            }
        }
        __syncthreads();
    }

    // ---- epilogue: add (bsv + bsve), store ----
    {
        u64 bc[8];
        #pragma unroll
        for (int p = 0; p < 8; p++)
            bc[p] = pack2(__ldg(bsv + ch0 + 2 * p)     + __ldg(bsve + ch0 + 2 * p),
                          __ldg(bsv + ch0 + 2 * p + 1) + __ldg(bsve + ch0 + 2 * p + 1));

        const size_t rbA = (((size_t)b * HH + iA) * WW) * OUTC + ch0;
        const size_t rbB = (((size_t)b * HH + iB) * WW) * OUTC + ch0;

        #pragma unroll
        for (int pp = 0; pp < 4; pp++) {
            ulonglong2 o;
            o.x = fadd2(accA0[2 * pp], bc[2 * pp]);
            o.y = fadd2(accA0[2 * pp + 1], bc[2 * pp + 1]);
            *(ulonglong2*)(out + rbA + (size_t)lane * OUTC + pp * 4) = o;
            o.x = fadd2(accB0[2 * pp], bc[2 * pp]);
            o.y = fadd2(accB0[2 * pp + 1], bc[2 * pp + 1]);
            *(ulonglong2*)(out + rbB + (size_t)lane * OUTC + pp * 4) = o;
        }
        if (w1ok) {
            #pragma unroll
            for (int pp = 0; pp < 4; pp++) {
                ulonglong2 o;
                o.x = fadd2(accA1[2 * pp], bc[2 * pp]);
                o.y = fadd2(accA1[2 * pp + 1], bc[2 * pp + 1]);
                *(ulonglong2*)(out + rbA + (size_t)(lane + 32) * OUTC + pp * 4) = o;
                o.x = fadd2(accB1[2 * pp], bc[2 * pp]);
                o.y = fadd2(accB1[2 * pp + 1], bc[2 * pp + 1]);
                *(ulonglong2*)(out + rbB + (size_t)(lane + 32) * OUTC + pp * 4) = o;
            }
        }
    }
}

// ============================================================
extern "C" void kernel_launch(void* const* d_in, const int* in_sizes, int n_in,
                              void* d_out, int out_size)
{
    const float* x    = (const float*)d_in[0];
    const float* w_q  = (const float*)d_in[1];
    const float* w_k  = (const float*)d_in[2];
    const float* w_v  = (const float*)d_in[3];
    const float* q_rel = (const float*)d_in[4];
    const float* k_rel = (const float*)d_in[5];
    const float* v_rel = (const float*)d_in[6];
    const float* g_q  = (const float*)d_in[7];
    const float* b_q  = (const float*)d_in[8];
    const float* g_k  = (const float*)d_in[9];
    const float* b_k  = (const float*)d_in[10];
    const float* g_v  = (const float*)d_in[11];
    const float* b_v  = (const float*)d_in[12];
    const float* g_qk = (const float*)d_in[13];
    const float* g_qr = (const float*)d_in[15];
    const float* g_kr = (const float*)d_in[17];
    const float* g_sv = (const float*)d_in[19];
    const float* b_sv = (const float*)d_in[20];
    const float* g_sve = (const float*)d_in[21];
    const float* b_sve = (const float*)d_in[22];

    const int proj_smem = (64 * 129 + 128 * 64) * sizeof(float);
    cudaFuncSetAttribute(proj_kernel, cudaFuncAttributeMaxDynamicSharedMemorySize, proj_smem);

    dim3 g1(4, (NB * HH * WW) / 64);
    proj_kernel<<<g1, 256, proj_smem>>>(x, w_q, w_k, w_v,
                                        g_q, b_q, g_k, b_k, g_v, b_v);

    dim3 g2(7, GRP, NB);               // 8 i-rows per CTA (4 warps × 2)
    attn_kernel<<<g2, 128>>>(q_rel, k_rel, v_rel,
                             g_qk, g_qr, g_kr,
                             g_sv, b_sv, g_sve, b_sve,
                             (float*)d_out);
}

// round 12
// speedup vs baseline: 3.6520x; 1.1495x over previous
#include <cuda_runtime.h>
#include <cstdint>

#define NB   32
#define HH   56
#define WW   56
#define CIN  128
#define OUTC 128
#define GRP  8
#define GC   16
#define GC2  8
#define REL  111     // 2*56-1
#define KS   12      // padded K row stride (words) — conflict-free LDS.128
#define VS   20      // padded V row stride (words) — conflict-free LDS.128
#define XSP  68      // transposed-A smem row pad (16B-aligned, kk stride)

#define BNSCALE 0.9995003746876562f   // 1/sqrt(1 + 1e-3)

typedef unsigned long long u64;

// ---- packed f32x2 helpers (FFMA2 path, sm_103a) ----
__device__ __forceinline__ u64 pack2(float lo, float hi) {
    u64 d; asm("mov.b64 %0, {%1, %2};" : "=l"(d) : "f"(lo), "f"(hi)); return d;
}
__device__ __forceinline__ float lo2(u64 v) {
    float f; asm("{\n\t.reg .f32 h;\n\tmov.b64 {%0, h}, %1;\n\t}" : "=f"(f) : "l"(v)); return f;
}
__device__ __forceinline__ float hi2(u64 v) {
    float f; asm("{\n\t.reg .f32 l;\n\tmov.b64 {l, %0}, %1;\n\t}" : "=f"(f) : "l"(v)); return f;
}
__device__ __forceinline__ u64 ffma2(u64 a, u64 b, u64 c) {
    u64 d; asm("fma.rn.f32x2 %0, %1, %2, %3;" : "=l"(d) : "l"(a), "l"(b), "l"(c)); return d;
}
__device__ __forceinline__ u64 fadd2(u64 a, u64 b) {
    u64 d; asm("add.rn.f32x2 %0, %1, %2;" : "=l"(d) : "l"(a), "l"(b)); return d;
}
__device__ __forceinline__ u64 fmul2(u64 a, u64 b) {
    u64 d; asm("mul.rn.f32x2 %0, %1, %2;" : "=l"(d) : "l"(a), "l"(b)); return d;
}
__device__ __forceinline__ void ld4(u64 dst[4], const float* p) {
    ulonglong2 a = *(const ulonglong2*)p;
    ulonglong2 b = *(const ulonglong2*)(p + 4);
    dst[0] = a.x; dst[1] = a.y; dst[2] = b.x; dst[3] = b.y;
}
__device__ __forceinline__ void ld8(u64 dst[8], const float* p) {
    ld4(dst, p); ld4(dst + 4, p + 8);
}

// ---- scratch (static device arrays; no allocation) ----
__device__ __align__(16) float g_qs[(size_t)NB * GRP * HH * WW * GC2];   // [b][g][i][w][c8]
__device__ __align__(16) float g_ks[(size_t)NB * GRP * HH * WW * GC2];   // [b][g][j][w][c8]
__device__ __align__(16) float g_vs[(size_t)NB * GRP * HH * WW * GC];    // [b][g][j][w][c16]

// ============================================================
// Kernel 1: fused QKV projection + BN.
// Transposed-A smem (broadcast a-loads), 8x4 per-thread tile,
// FFMA2 row-pairs, vectorized grouped-scatter epilogue.
// grid (2, 1568): cb=0 -> q|k (128 cols), cb=1 -> v (128 cols)
// ============================================================
__global__ __launch_bounds__(256, 2) void proj_kernel(
    const float* __restrict__ x,
    const float* __restrict__ wq, const float* __restrict__ wk, const float* __restrict__ wv,
    const float* __restrict__ gq, const float* __restrict__ bq,
    const float* __restrict__ gk, const float* __restrict__ bk,
    const float* __restrict__ gv, const float* __restrict__ bv)
{
    extern __shared__ float smem[];
    float* xs = smem;                    // [128 kk][XSP] transposed x tile (rows in cols)
    float* ws = smem + 128 * XSP;        // [128 kk][128 cols]

    const int cb = blockIdx.x;           // 0: q|k, 1: v
    const int rb = blockIdx.y;
    const int t  = threadIdx.x;
    const int row0 = rb * 64;

    // ---- fill xs transposed: thread owns k = t&127, rows rh*32..+31 ----
    {
        const int k = t & 127, rh = t >> 7;
        const float* src = x + (size_t)(row0 + rh * 32) * CIN + k;
        float* dst = xs + k * XSP + rh * 32;
        #pragma unroll 8
        for (int r = 0; r < 32; r++) dst[r] = src[(size_t)r * CIN];
    }
    // ---- fill ws [128][128] ----
    if (cb == 0) {
        #pragma unroll
        for (int p = 0; p < 16; p++) {
            const int idx = t + 256 * p;              // 0..4095 float4s
            const int kk = idx >> 5, c4 = (idx & 31) * 4;
            float4 v = (c4 < 64) ? *(const float4*)(wq + kk * 64 + c4)
                                 : *(const float4*)(wk + kk * 64 + (c4 - 64));
            *(float4*)(ws + kk * 128 + c4) = v;
        }
    } else {
        #pragma unroll
        for (int p = 0; p < 16; p++) {
            const int idx = t + 256 * p;
            const int kk = idx >> 5, c4 = (idx & 31) * 4;
            *(float4*)(ws + kk * 128 + c4) = *(const float4*)(wv + kk * 128 + c4);
        }
    }
    __syncthreads();

    const int ty = t >> 5;     // 0..7  -> rows ty*8 .. ty*8+7
    const int tx = t & 31;     // cols tx*4 .. tx*4+3

    u64 acc[4][4];             // [row-pair][col]; u64 = (row 2rp lo, row 2rp+1 hi)
    #pragma unroll
    for (int rp = 0; rp < 4; rp++)
        #pragma unroll
        for (int c = 0; c < 4; c++) acc[rp][c] = 0ull;

    #pragma unroll 4
    for (int kk = 0; kk < 128; kk++) {
        const float* ap = xs + kk * XSP + ty * 8;
        ulonglong2 aA = *(const ulonglong2*)ap;        // rows (0,1),(2,3)
        ulonglong2 aB = *(const ulonglong2*)(ap + 4);  // rows (4,5),(6,7)
        float4 bf = *(const float4*)(ws + kk * 128 + tx * 4);
        u64 b0 = pack2(bf.x, bf.x), b1 = pack2(bf.y, bf.y);
        u64 b2 = pack2(bf.z, bf.z), b3 = pack2(bf.w, bf.w);
        acc[0][0] = ffma2(aA.x, b0, acc[0][0]);
        acc[0][1] = ffma2(aA.x, b1, acc[0][1]);
        acc[0][2] = ffma2(aA.x, b2, acc[0][2]);
        acc[0][3] = ffma2(aA.x, b3, acc[0][3]);
        acc[1][0] = ffma2(aA.y, b0, acc[1][0]);
        acc[1][1] = ffma2(aA.y, b1, acc[1][1]);
        acc[1][2] = ffma2(aA.y, b2, acc[1][2]);
        acc[1][3] = ffma2(aA.y, b3, acc[1][3]);
        acc[2][0] = ffma2(aB.x, b0, acc[2][0]);
        acc[2][1] = ffma2(aB.x, b1, acc[2][1]);
        acc[2][2] = ffma2(aB.x, b2, acc[2][2]);
        acc[2][3] = ffma2(aB.x, b3, acc[2][3]);
        acc[3][0] = ffma2(aB.y, b0, acc[3][0]);
        acc[3][1] = ffma2(aB.y, b1, acc[3][1]);
        acc[3][2] = ffma2(aB.y, b2, acc[3][2]);
        acc[3][3] = ffma2(aB.y, b3, acc[3][3]);
    }

    // ---- epilogue: BN + grouped scatter (STG.128) ----
    // channel setup for this thread's 4 contiguous columns
    float sc[4], be[4];
    float* dstbase;
    int gi, c0, ld;
    if (cb == 0) {
        if (tx < 16) {   // q: ch = tx*4 .. +3
            const int ch = tx * 4;
            #pragma unroll
            for (int c = 0; c < 4; c++) { sc[c] = __ldg(gq + ch + c) * BNSCALE; be[c] = __ldg(bq + ch + c); }
            gi = ch >> 3; c0 = ch & 7; ld = GC2; dstbase = g_qs;
        } else {         // k: ch = tx*4-64
            const int ch = tx * 4 - 64;
            #pragma unroll
            for (int c = 0; c < 4; c++) { sc[c] = __ldg(gk + ch + c) * BNSCALE; be[c] = __ldg(bk + ch + c); }
            gi = ch >> 3; c0 = ch & 7; ld = GC2; dstbase = g_ks;
        }
    } else {             // v: cv = tx*4
        const int cv = tx * 4;
        #pragma unroll
        for (int c = 0; c < 4; c++) { sc[c] = __ldg(gv + cv + c) * BNSCALE; be[c] = __ldg(bv + cv + c); }
        gi = cv >> 4; c0 = cv & 15; ld = GC; dstbase = g_vs;
    }

    #pragma unroll
    for (int rp = 0; rp < 4; rp++) {
        #pragma unroll
        for (int half = 0; half < 2; half++) {
            const int row = row0 + ty * 8 + rp * 2 + half;
            const int b = row / (HH * WW);
            const int rem = row - b * (HH * WW);
            const int h = rem / WW, w = rem - (rem / WW) * WW;
            float4 o;
            if (half == 0) {
                o.x = fmaf(lo2(acc[rp][0]), sc[0], be[0]);
                o.y = fmaf(lo2(acc[rp][1]), sc[1], be[1]);
                o.z = fmaf(lo2(acc[rp][2]), sc[2], be[2]);
                o.w = fmaf(lo2(acc[rp][3]), sc[3], be[3]);
            } else {
                o.x = fmaf(hi2(acc[rp][0]), sc[0], be[0]);
                o.y = fmaf(hi2(acc[rp][1]), sc[1], be[1]);
                o.z = fmaf(hi2(acc[rp][2]), sc[2], be[2]);
                o.w = fmaf(hi2(acc[rp][3]), sc[3], be[3]);
            }
            *(float4*)(dstbase + ((((size_t)b * GRP + gi) * HH + h) * WW + w) * ld + c0) = o;
        }
    }
}

// ============================================================
// Kernel 2: fused attention (unchanged from R11 best).
// 128 threads = 4 warps; warp owns 2 i-rows; packed f32x2 math;
// merged sv/sve accumulators. grid (7, 8, 32).
// ============================================================
__device__ __forceinline__ float logit8(const u64 qv[4], const u64 k[4],
                                        const u64 qe[4], const u64 ke[4]) {
    u64 s = fmul2(k[0], ke[0]);
    s = ffma2(k[1], ke[1], s);
    s = ffma2(k[2], ke[2], s);
    s = ffma2(k[3], ke[3], s);
    s = ffma2(qv[0], fadd2(k[0], qe[0]), s);
    s = ffma2(qv[1], fadd2(k[1], qe[1]), s);
    s = ffma2(qv[2], fadd2(k[2], qe[2]), s);
    s = ffma2(qv[3], fadd2(k[3], qe[3]), s);
    return lo2(s) + hi2(s);
}

__device__ __forceinline__ void softmax2(float L0, float L1, bool ok,
                                         float& P0, float& P1) {
    float m = fmaxf(L0, ok ? L1 : -1e30f);
    #pragma unroll
    for (int o = 16; o; o >>= 1) m = fmaxf(m, __shfl_xor_sync(0xffffffffu, m, o));
    float e0 = __expf(L0 - m);
    float e1 = ok ? __expf(L1 - m) : 0.f;
    float s = e0 + e1;
    #pragma unroll
    for (int o = 16; o; o >>= 1) s += __shfl_xor_sync(0xffffffffu, s, o);
    const float inv = __fdividef(1.f, s);
    P0 = e0 * inv; P1 = e1 * inv;
}

__global__ __launch_bounds__(128, 3) void attn_kernel(
    const float* __restrict__ qrel, const float* __restrict__ krel, const float* __restrict__ vrel,
    const float* __restrict__ gqk,
    const float* __restrict__ gqr,
    const float* __restrict__ gkr,
    const float* __restrict__ gsv, const float* __restrict__ bsv,
    const float* __restrict__ gsve, const float* __restrict__ bsve,
    float* __restrict__ out)
{
    __shared__ __align__(16) float kbuf[2][64 * KS];
    __shared__ __align__(16) float vbuf[2][64 * VS];     // pre-scaled by gsv
    __shared__ __align__(16) float qrel_s[REL * GC2];    // * gqr/gqk
    __shared__ __align__(16) float krel_s[REL * GC2];    // * gkr*BNSCALE
    __shared__ __align__(16) float vrel_s[REL * GC];     // * gsve*BNSCALE

    const int it = blockIdx.x, g = blockIdx.y, b = blockIdx.z;
    const int t = threadIdx.x, lane = t & 31, wid = t >> 5;
    const int iA = it * 8 + wid * 2, iB = iA + 1;
    const size_t bgrow = ((size_t)b * GRP + g) * HH;
    const int ch0 = g * GC;

    const float sqk = gqk[g] * BNSCALE;
    const float fqr = gqr[g] / gqk[g];
    const float skr = gkr[g] * BNSCALE;

    for (int idx = t; idx < REL * GC2; idx += 128) {
        qrel_s[idx] = qrel[idx] * fqr;
        krel_s[idx] = krel[idx] * skr;
    }
    {   // vrel scaled by gsve (c = idx&15 constant per thread under stride 128)
        const float s2 = __ldg(gsve + ch0 + (t & 15)) * BNSCALE;
        for (int idx = t; idx < REL * GC; idx += 128) vrel_s[idx] = vrel[idx] * s2;
    }

    // zero pad rows (w in [56,64))
    if (t < 64) {
        const int w = 56 + (t >> 3), c = t & 7;
        kbuf[0][w * KS + c] = 0.f; kbuf[1][w * KS + c] = 0.f;
    }
    {
        const int w = 56 + (t >> 4), c = t & 15;
        vbuf[0][w * VS + c] = 0.f; vbuf[1][w * VS + c] = 0.f;
    }

    // per-thread V staging scale pairs (c4 = (t&3)*4, invariant under +128)
    const int c4 = (t & 3) * 4;
    const u64 s1p0 = pack2(__ldg(gsv + ch0 + c4 + 0) * BNSCALE,
                           __ldg(gsv + ch0 + c4 + 1) * BNSCALE);
    const u64 s1p1 = pack2(__ldg(gsv + ch0 + c4 + 2) * BNSCALE,
                           __ldg(gsv + ch0 + c4 + 3) * BNSCALE);

    // j = 0 fill
    {
        const ulonglong2* k2 = (const ulonglong2*)(g_ks + bgrow * (WW * GC2));
        const ulonglong2* v2 = (const ulonglong2*)(g_vs + bgrow * (WW * GC));
        if (t < 112) *(ulonglong2*)&kbuf[0][(t >> 1) * KS + (t & 1) * 4] = k2[t];
        ulonglong2 sv = v2[t];
        sv.x = fmul2(sv.x, s1p0); sv.y = fmul2(sv.y, s1p1);
        *(ulonglong2*)&vbuf[0][(t >> 2) * VS + c4] = sv;
        if (t < 96) {
            ulonglong2 sw = v2[t + 128];
            sw.x = fmul2(sw.x, s1p0); sw.y = fmul2(sw.y, s1p1);
            *(ulonglong2*)&vbuf[0][((t + 128) >> 2) * VS + c4] = sw;
        }
    }

    // q registers (both i-rows, both w slots), pre-scaled by sqk
    const bool w1ok = (lane < WW - 32);
    const u64 sqk2 = pack2(sqk, sqk);
    u64 qvA0[4], qvA1[4], qvB0[4], qvB1[4];
    {
        const float* qrA = g_qs + (bgrow + iA) * (WW * GC2);
        const float* qrB = g_qs + (bgrow + iB) * (WW * GC2);
        u64 tmp[4];
        ld4(tmp, qrA + lane * GC2);
        #pragma unroll
        for (int p = 0; p < 4; p++) qvA0[p] = fmul2(tmp[p], sqk2);
        ld4(tmp, qrB + lane * GC2);
        #pragma unroll
        for (int p = 0; p < 4; p++) qvB0[p] = fmul2(tmp[p], sqk2);
        if (w1ok) {
            ld4(tmp, qrA + (lane + 32) * GC2);
            #pragma unroll
            for (int p = 0; p < 4; p++) qvA1[p] = fmul2(tmp[p], sqk2);
            ld4(tmp, qrB + (lane + 32) * GC2);
            #pragma unroll
            for (int p = 0; p < 4; p++) qvB1[p] = fmul2(tmp[p], sqk2);
        } else {
            #pragma unroll
            for (int p = 0; p < 4; p++) { qvA1[p] = 0ull; qvB1[p] = 0ull; }
        }
    }
    __syncthreads();

    u64 accA0[8], accA1[8], accB0[8], accB1[8];
    #pragma unroll
    for (int p = 0; p < 8; p++) { accA0[p] = 0ull; accA1[p] = 0ull; accB0[p] = 0ull; accB1[p] = 0ull; }

    for (int j = 0; j < HH; j++) {
        const int cur = j & 1, nxt = cur ^ 1;

        // stage next-j K/V rows (V pre-scaled by gsv)
        ulonglong2 stk, stv0, stv1;
        if (j + 1 < HH) {
            const ulonglong2* k2 = (const ulonglong2*)(g_ks + (bgrow + j + 1) * (WW * GC2));
            const ulonglong2* v2 = (const ulonglong2*)(g_vs + (bgrow + j + 1) * (WW * GC));
            if (t < 112) stk = k2[t];
            stv0 = v2[t];
            if (t < 96) stv1 = v2[t + 128];
        }

        // ---- logits (2 i-rows × 2 slots), K regs shared ----
        u64 k0[4], k1[4];
        ld4(k0, kbuf[cur] + lane * KS);
        ld4(k1, kbuf[cur] + (lane + 32) * KS);

        u64 qeA[4], keA[4], qeB[4], keB[4];
        ld4(qeA, qrel_s + (iA - j + HH - 1) * GC2);
        ld4(keA, krel_s + (j - iA + HH - 1) * GC2);
        ld4(qeB, qrel_s + (iB - j + HH - 1) * GC2);
        ld4(keB, krel_s + (j - iB + HH - 1) * GC2);

        const float LA0 = logit8(qvA0, k0, qeA, keA);
        const float LA1 = logit8(qvA1, k1, qeA, keA);
        const float LB0 = logit8(qvB0, k0, qeB, keB);
        const float LB1 = logit8(qvB1, k1, qeB, keB);

        // ---- warp-local softmax (independent per i-row) ----
        float PA0, PA1, PB0, PB1;
        softmax2(LA0, LA1, w1ok, PA0, PA1);
        softmax2(LB0, LB1, w1ok, PB0, PB1);

        // ---- merged accumulation: acc += P * (V*s1 + ve*s2) ----
        {
            u64 v0[8], v1[8];
            ld8(v0, vbuf[cur] + lane * VS);
            ld8(v1, vbuf[cur] + (lane + 32) * VS);

            u64 veA[8];
            ld8(veA, vrel_s + (j - iA + HH - 1) * GC);
            const u64 pA0 = pack2(PA0, PA0), pA1 = pack2(PA1, PA1);
            #pragma unroll
            for (int p = 0; p < 8; p++) {
                accA0[p] = ffma2(pA0, fadd2(v0[p], veA[p]), accA0[p]);
                accA1[p] = ffma2(pA1, fadd2(v1[p], veA[p]), accA1[p]);
            }
            u64 veB[8];
            ld8(veB, vrel_s + (j - iB + HH - 1) * GC);
            const u64 pB0 = pack2(PB0, PB0), pB1 = pack2(PB1, PB1);
            #pragma unroll
            for (int p = 0; p < 8; p++) {
                accB0[p] = ffma2(pB0, fadd2(v0[p], veB[p]), accB0[p]);
                accB1[p] = ffma2(pB1, fadd2(v1[p], veB[p]), accB1[p]);
            }
        }

        // commit staged rows
        if (j + 1 < HH) {
            if (t < 112) *(ulonglong2*)&kbuf[nxt][(t >> 1) * KS + (t & 1) * 4] = stk;
            stv0.x = fmul2(stv0.x, s1p0); stv0.y = fmul2(stv0.y, s1p1);
            *(ulonglong2*)&vbuf[nxt][(t >> 2) * VS + c4] = stv0;
            if (t < 96) {
                stv1.x = fmul2(stv1.x, s1p0); stv1.y = fmul2(stv1.y, s1p1);
                *(ulonglong2*)&vbuf[nxt][((t + 128) >> 2) * VS + c4] = stv1;
            }
        }
        __syncthreads();
    }

    // ---- epilogue: add (bsv + bsve), store ----
    {
        u64 bc[8];
        #pragma unroll
        for (int p = 0; p < 8; p++)
            bc[p] = pack2(__ldg(bsv + ch0 + 2 * p)     + __ldg(bsve + ch0 + 2 * p),
                          __ldg(bsv + ch0 + 2 * p + 1) + __ldg(bsve + ch0 + 2 * p + 1));

        const size_t rbA = (((size_t)b * HH + iA) * WW) * OUTC + ch0;
        const size_t rbB = (((size_t)b * HH + iB) * WW) * OUTC + ch0;

        #pragma unroll
        for (int pp = 0; pp < 4; pp++) {
            ulonglong2 o;
            o.x = fadd2(accA0[2 * pp], bc[2 * pp]);
            o.y = fadd2(accA0[2 * pp + 1], bc[2 * pp + 1]);
            *(ulonglong2*)(out + rbA + (size_t)lane * OUTC + pp * 4) = o;
            o.x = fadd2(accB0[2 * pp], bc[2 * pp]);
            o.y = fadd2(accB0[2 * pp + 1], bc[2 * pp + 1]);
            *(ulonglong2*)(out + rbB + (size_t)lane * OUTC + pp * 4) = o;
        }
        if (w1ok) {
            #pragma unroll
            for (int pp = 0; pp < 4; pp++) {
                ulonglong2 o;
                o.x = fadd2(accA1[2 * pp], bc[2 * pp]);
                o.y = fadd2(accA1[2 * pp + 1], bc[2 * pp + 1]);
                *(ulonglong2*)(out + rbA + (size_t)(lane + 32) * OUTC + pp * 4) = o;
                o.x = fadd2(accB1[2 * pp], bc[2 * pp]);
                o.y = fadd2(accB1[2 * pp + 1], bc[2 * pp + 1]);
                *(ulonglong2*)(out + rbB + (size_t)(lane + 32) * OUTC + pp * 4) = o;
            }
        }
    }
}

// ============================================================
extern "C" void kernel_launch(void* const* d_in, const int* in_sizes, int n_in,
                              void* d_out, int out_size)
{
    const float* x    = (const float*)d_in[0];
    const float* w_q  = (const float*)d_in[1];
    const float* w_k  = (const float*)d_in[2];
    const float* w_v  = (const float*)d_in[3];
    const float* q_rel = (const float*)d_in[4];
    const float* k_rel = (const float*)d_in[5];
    const float* v_rel = (const float*)d_in[6];
    const float* g_q  = (const float*)d_in[7];
    const float* b_q  = (const float*)d_in[8];
    const float* g_k  = (const float*)d_in[9];
    const float* b_k  = (const float*)d_in[10];
    const float* g_v  = (const float*)d_in[11];
    const float* b_v  = (const float*)d_in[12];
    const float* g_qk = (const float*)d_in[13];
    const float* g_qr = (const float*)d_in[15];
    const float* g_kr = (const float*)d_in[17];
    const float* g_sv = (const float*)d_in[19];
    const float* b_sv = (const float*)d_in[20];
    const float* g_sve = (const float*)d_in[21];
    const float* b_sve = (const float*)d_in[22];

    const int proj_smem = (128 * XSP + 128 * 128) * sizeof(float);   // 100352 B
    cudaFuncSetAttribute(proj_kernel, cudaFuncAttributeMaxDynamicSharedMemorySize, proj_smem);

    dim3 g1(2, (NB * HH * WW) / 64);   // (2, 1568)
    proj_kernel<<<g1, 256, proj_smem>>>(x, w_q, w_k, w_v,
                                        g_q, b_q, g_k, b_k, g_v, b_v);

    dim3 g2(7, GRP, NB);               // 8 i-rows per CTA (4 warps × 2)
    attn_kernel<<<g2, 128>>>(q_rel, k_rel, v_rel,
                             g_qk, g_qr, g_kr,
                             g_sv, b_sv, g_sve, b_sve,
                             (float*)d_out);
}

// round 14
// speedup vs baseline: 4.3005x; 1.1776x over previous
#include <cuda_runtime.h>
#include <cstdint>

#define NB   32
#define HH   56
#define WW   56
#define CIN  128
#define OUTC 128
#define GRP  8
#define GC   16
#define GC2  8
#define REL  111     // 2*56-1
#define KS   12      // padded K row stride (words) — conflict-free LDS.128
#define VS   20      // padded V row stride (words) — conflict-free LDS.128
#define XSP  68      // transposed-A smem row pad (proj)

#define BNSCALE 0.9995003746876562f   // 1/sqrt(1 + 1e-3)

typedef unsigned long long u64;

// ---- packed f32x2 helpers (FFMA2 path, sm_103a) ----
__device__ __forceinline__ u64 pack2(float lo, float hi) {
    u64 d; asm("mov.b64 %0, {%1, %2};" : "=l"(d) : "f"(lo), "f"(hi)); return d;
}
__device__ __forceinline__ float lo2(u64 v) {
    float f; asm("{\n\t.reg .f32 h;\n\tmov.b64 {%0, h}, %1;\n\t}" : "=f"(f) : "l"(v)); return f;
}
__device__ __forceinline__ float hi2(u64 v) {
    float f; asm("{\n\t.reg .f32 l;\n\tmov.b64 {l, %0}, %1;\n\t}" : "=f"(f) : "l"(v)); return f;
}
__device__ __forceinline__ u64 ffma2(u64 a, u64 b, u64 c) {
    u64 d; asm("fma.rn.f32x2 %0, %1, %2, %3;" : "=l"(d) : "l"(a), "l"(b), "l"(c)); return d;
}
__device__ __forceinline__ u64 fadd2(u64 a, u64 b) {
    u64 d; asm("add.rn.f32x2 %0, %1, %2;" : "=l"(d) : "l"(a), "l"(b)); return d;
}
__device__ __forceinline__ u64 fmul2(u64 a, u64 b) {
    u64 d; asm("mul.rn.f32x2 %0, %1, %2;" : "=l"(d) : "l"(a), "l"(b)); return d;
}
__device__ __forceinline__ void ld4(u64 dst[4], const float* p) {
    ulonglong2 a = *(const ulonglong2*)p;
    ulonglong2 b = *(const ulonglong2*)(p + 4);
    dst[0] = a.x; dst[1] = a.y; dst[2] = b.x; dst[3] = b.y;
}
__device__ __forceinline__ void ld8(u64 dst[8], const float* p) {
    ld4(dst, p); ld4(dst + 4, p + 8);
}

// ---- cp.async ----
__device__ __forceinline__ void cp16(const void* smem_dst, const void* gsrc) {
    unsigned d = (unsigned)__cvta_generic_to_shared(smem_dst);
    asm volatile("cp.async.cg.shared.global [%0], [%1], 16;" :: "r"(d), "l"(gsrc));
}
#define CP_COMMIT() asm volatile("cp.async.commit_group;")
#define CP_WAIT0()  asm volatile("cp.async.wait_group 0;")

// ---- warp max via single REDUX (monotonic float<->u32 key) ----
__device__ __forceinline__ float warp_max_redux(float v) {
    unsigned u = __float_as_uint(v);
    unsigned key = u ^ (unsigned)(((int)u >> 31) | 0x80000000);
    unsigned r;
    asm("redux.sync.max.u32 %0, %1, 0xffffffff;" : "=r"(r) : "r"(key));
    unsigned back = r ^ (unsigned)(((int)(~r) >> 31) | 0x80000000);
    return __uint_as_float(back);
}

// ---- scratch (static device arrays; no allocation) ----
__device__ __align__(16) float g_qs[(size_t)NB * GRP * HH * WW * GC2];   // [b][g][i][w][c8]
__device__ __align__(16) float g_ks[(size_t)NB * GRP * HH * WW * GC2];   // [b][g][j][w][c8]
__device__ __align__(16) float g_vs[(size_t)NB * GRP * HH * WW * GC];    // [b][g][j][w][c16]

// ============================================================
// Kernel 1: fused QKV projection + BN (unchanged from R12).
// ============================================================
__global__ __launch_bounds__(256, 2) void proj_kernel(
    const float* __restrict__ x,
    const float* __restrict__ wq, const float* __restrict__ wk, const float* __restrict__ wv,
    const float* __restrict__ gq, const float* __restrict__ bq,
    const float* __restrict__ gk, const float* __restrict__ bk,
    const float* __restrict__ gv, const float* __restrict__ bv)
{
    extern __shared__ float smem[];
    float* xs = smem;                    // [128 kk][XSP]
    float* ws = smem + 128 * XSP;        // [128 kk][128 cols]

    const int cb = blockIdx.x;
    const int rb = blockIdx.y;
    const int t  = threadIdx.x;
    const int row0 = rb * 64;

    {
        const int k = t & 127, rh = t >> 7;
        const float* src = x + (size_t)(row0 + rh * 32) * CIN + k;
        float* dst = xs + k * XSP + rh * 32;
        #pragma unroll 8
        for (int r = 0; r < 32; r++) dst[r] = src[(size_t)r * CIN];
    }
    if (cb == 0) {
        #pragma unroll
        for (int p = 0; p < 16; p++) {
            const int idx = t + 256 * p;
            const int kk = idx >> 5, c4 = (idx & 31) * 4;
            float4 v = (c4 < 64) ? *(const float4*)(wq + kk * 64 + c4)
                                 : *(const float4*)(wk + kk * 64 + (c4 - 64));
            *(float4*)(ws + kk * 128 + c4) = v;
        }
    } else {
        #pragma unroll
        for (int p = 0; p < 16; p++) {
            const int idx = t + 256 * p;
            const int kk = idx >> 5, c4 = (idx & 31) * 4;
            *(float4*)(ws + kk * 128 + c4) = *(const float4*)(wv + kk * 128 + c4);
        }
    }
    __syncthreads();

    const int ty = t >> 5, tx = t & 31;
    u64 acc[4][4];
    #pragma unroll
    for (int rp = 0; rp < 4; rp++)
        #pragma unroll
        for (int c = 0; c < 4; c++) acc[rp][c] = 0ull;

    #pragma unroll 4
    for (int kk = 0; kk < 128; kk++) {
        const float* ap = xs + kk * XSP + ty * 8;
        ulonglong2 aA = *(const ulonglong2*)ap;
        ulonglong2 aB = *(const ulonglong2*)(ap + 4);
        float4 bf = *(const float4*)(ws + kk * 128 + tx * 4);
        u64 b0 = pack2(bf.x, bf.x), b1 = pack2(bf.y, bf.y);
        u64 b2 = pack2(bf.z, bf.z), b3 = pack2(bf.w, bf.w);
        acc[0][0] = ffma2(aA.x, b0, acc[0][0]);
        acc[0][1] = ffma2(aA.x, b1, acc[0][1]);
        acc[0][2] = ffma2(aA.x, b2, acc[0][2]);
        acc[0][3] = ffma2(aA.x, b3, acc[0][3]);
        acc[1][0] = ffma2(aA.y, b0, acc[1][0]);
        acc[1][1] = ffma2(aA.y, b1, acc[1][1]);
        acc[1][2] = ffma2(aA.y, b2, acc[1][2]);
        acc[1][3] = ffma2(aA.y, b3, acc[1][3]);
        acc[2][0] = ffma2(aB.x, b0, acc[2][0]);
        acc[2][1] = ffma2(aB.x, b1, acc[2][1]);
        acc[2][2] = ffma2(aB.x, b2, acc[2][2]);
        acc[2][3] = ffma2(aB.x, b3, acc[2][3]);
        acc[3][0] = ffma2(aB.y, b0, acc[3][0]);
        acc[3][1] = ffma2(aB.y, b1, acc[3][1]);
        acc[3][2] = ffma2(aB.y, b2, acc[3][2]);
        acc[3][3] = ffma2(aB.y, b3, acc[3][3]);
    }

    float sc[4], be[4];
    float* dstbase;
    int gi, c0, ld;
    if (cb == 0) {
        if (tx < 16) {
            const int ch = tx * 4;
            #pragma unroll
            for (int c = 0; c < 4; c++) { sc[c] = __ldg(gq + ch + c) * BNSCALE; be[c] = __ldg(bq + ch + c); }
            gi = ch >> 3; c0 = ch & 7; ld = GC2; dstbase = g_qs;
        } else {
            const int ch = tx * 4 - 64;
            #pragma unroll
            for (int c = 0; c < 4; c++) { sc[c] = __ldg(gk + ch + c) * BNSCALE; be[c] = __ldg(bk + ch + c); }
            gi = ch >> 3; c0 = ch & 7; ld = GC2; dstbase = g_ks;
        }
    } else {
        const int cv = tx * 4;
        #pragma unroll
        for (int c = 0; c < 4; c++) { sc[c] = __ldg(gv + cv + c) * BNSCALE; be[c] = __ldg(bv + cv + c); }
        gi = cv >> 4; c0 = cv & 15; ld = GC; dstbase = g_vs;
    }

    #pragma unroll
    for (int rp = 0; rp < 4; rp++) {
        #pragma unroll
        for (int half = 0; half < 2; half++) {
            const int row = row0 + ty * 8 + rp * 2 + half;
            const int b = row / (HH * WW);
            const int rem = row - b * (HH * WW);
            const int h = rem / WW, w = rem - (rem / WW) * WW;
            float4 o;
            if (half == 0) {
                o.x = fmaf(lo2(acc[rp][0]), sc[0], be[0]);
                o.y = fmaf(lo2(acc[rp][1]), sc[1], be[1]);
                o.z = fmaf(lo2(acc[rp][2]), sc[2], be[2]);
                o.w = fmaf(lo2(acc[rp][3]), sc[3], be[3]);
            } else {
                o.x = fmaf(hi2(acc[rp][0]), sc[0], be[0]);
                o.y = fmaf(hi2(acc[rp][1]), sc[1], be[1]);
                o.z = fmaf(hi2(acc[rp][2]), sc[2], be[2]);
                o.w = fmaf(hi2(acc[rp][3]), sc[3], be[3]);
            }
            *(float4*)(dstbase + ((((size_t)b * GRP + gi) * HH + h) * WW + w) * ld + c0) = o;
        }
    }
}

// ============================================================
// Kernel 2: fused attention. 4 warps × 2 i-rows; 2 j-rows per
// iteration (independent chains); cp.async staging; REDUX max;
// raw-V buffers with gsv fold moved to epilogue. grid (7,8,32).
// ============================================================
__device__ __forceinline__ float logit8(const u64 qv[4], const u64 k[4],
                                        const u64 qe[4], const u64 ke[4]) {
    u64 s0 = fmul2(k[0], ke[0]);
    u64 s1 = fmul2(k[1], ke[1]);
    s0 = ffma2(k[2], ke[2], s0);
    s1 = ffma2(k[3], ke[3], s1);
    s0 = ffma2(qv[0], fadd2(k[0], qe[0]), s0);
    s1 = ffma2(qv[1], fadd2(k[1], qe[1]), s1);
    s0 = ffma2(qv[2], fadd2(k[2], qe[2]), s0);
    s1 = ffma2(qv[3], fadd2(k[3], qe[3]), s1);
    u64 s = fadd2(s0, s1);
    return lo2(s) + hi2(s);
}

__device__ __forceinline__ void softmax2(float L0, float L1, bool ok,
                                         float& P0, float& P1) {
    float m = warp_max_redux(fmaxf(L0, ok ? L1 : -1e30f));
    float e0 = __expf(L0 - m);
    float e1 = ok ? __expf(L1 - m) : 0.f;
    float s = e0 + e1;
    #pragma unroll
    for (int o = 16; o; o >>= 1) s += __shfl_xor_sync(0xffffffffu, s, o);
    const float inv = __fdividef(1.f, s);
    P0 = e0 * inv; P1 = e1 * inv;
}

__global__ __launch_bounds__(128, 3) void attn_kernel(
    const float* __restrict__ qrel, const float* __restrict__ krel, const float* __restrict__ vrel,
    const float* __restrict__ gqk,
    const float* __restrict__ gqr,
    const float* __restrict__ gkr,
    const float* __restrict__ gsv, const float* __restrict__ bsv,
    const float* __restrict__ gsve, const float* __restrict__ bsve,
    float* __restrict__ out)
{
    __shared__ __align__(16) float kbuf[2][2 * 64 * KS];   // [buf][row(2)][64*KS]
    __shared__ __align__(16) float vbuf[2][2 * 64 * VS];   // raw V
    __shared__ __align__(16) float qrel_s[REL * GC2];      // * gqr/gqk
    __shared__ __align__(16) float krel_s[REL * GC2];      // * gkr*BNSCALE
    __shared__ __align__(16) float vrel_s[REL * GC];       // * gsve/gsv

    const int it = blockIdx.x, g = blockIdx.y, b = blockIdx.z;
    const int t = threadIdx.x, lane = t & 31, wid = t >> 5;
    const int iA = it * 8 + wid * 2, iB = iA + 1;
    const size_t bgrow = ((size_t)b * GRP + g) * HH;
    const int ch0 = g * GC;

    // ---- prefetch rows 0,1 immediately ----
    auto prefetch2 = [&](int bf, int jr) {
        const float* k0p = g_ks + (bgrow + jr) * (WW * GC2);
        const float* v0p = g_vs + (bgrow + jr) * (WW * GC);
        if (t < 112) {
            const int w = t >> 1, c = (t & 1) * 4;
            cp16(&kbuf[bf][w * KS + c], k0p + t * 4);
            cp16(&kbuf[bf][64 * KS + w * KS + c], k0p + WW * GC2 + t * 4);
        }
        {
            const int w = t >> 2, c = (t & 3) * 4;
            cp16(&vbuf[bf][w * VS + c], v0p + t * 4);
            cp16(&vbuf[bf][64 * VS + w * VS + c], v0p + WW * GC + t * 4);
        }
        if (t < 96) {
            const int t2 = t + 128;
            const int w = t2 >> 2, c = (t2 & 3) * 4;
            cp16(&vbuf[bf][w * VS + c], v0p + t2 * 4);
            cp16(&vbuf[bf][64 * VS + w * VS + c], v0p + WW * GC + t2 * 4);
        }
    };
    prefetch2(0, 0);
    CP_COMMIT();

    const float sqk = gqk[g] * BNSCALE;
    const float fqr = gqr[g] / gqk[g];
    const float skr = gkr[g] * BNSCALE;

    for (int idx = t; idx < REL * GC2; idx += 128) {
        qrel_s[idx] = qrel[idx] * fqr;
        krel_s[idx] = krel[idx] * skr;
    }
    {   // vrel scaled by gsve/gsv (c = idx&15 constant per thread, 128 | stride)
        const float s2 = __ldg(gsve + ch0 + (t & 15)) / __ldg(gsv + ch0 + (t & 15));
        for (int idx = t; idx < REL * GC; idx += 128) vrel_s[idx] = vrel[idx] * s2;
    }

    // zero pad rows (w in [56,64)) of all buffers/rows
    if (t < 64) {
        const int w = 56 + (t >> 3), c = t & 7;
        #pragma unroll
        for (int bf = 0; bf < 2; bf++)
            #pragma unroll
            for (int r = 0; r < 2; r++) kbuf[bf][r * 64 * KS + w * KS + c] = 0.f;
    }
    {
        const int w = 56 + (t >> 4), c = t & 15;
        #pragma unroll
        for (int bf = 0; bf < 2; bf++)
            #pragma unroll
            for (int r = 0; r < 2; r++) vbuf[bf][r * 64 * VS + w * VS + c] = 0.f;
    }

    // q registers (both i-rows, both w slots), pre-scaled by sqk
    const bool w1ok = (lane < WW - 32);
    const u64 sqk2 = pack2(sqk, sqk);
    u64 qvA0[4], qvA1[4], qvB0[4], qvB1[4];
    {
        const float* qrA = g_qs + (bgrow + iA) * (WW * GC2);
        const float* qrB = g_qs + (bgrow + iB) * (WW * GC2);
        u64 tmp[4];
        ld4(tmp, qrA + lane * GC2);
        #pragma unroll
        for (int p = 0; p < 4; p++) qvA0[p] = fmul2(tmp[p], sqk2);
        ld4(tmp, qrB + lane * GC2);
        #pragma unroll
        for (int p = 0; p < 4; p++) qvB0[p] = fmul2(tmp[p], sqk2);
        if (w1ok) {
            ld4(tmp, qrA + (lane + 32) * GC2);
            #pragma unroll
            for (int p = 0; p < 4; p++) qvA1[p] = fmul2(tmp[p], sqk2);
            ld4(tmp, qrB + (lane + 32) * GC2);
            #pragma unroll
            for (int p = 0; p < 4; p++) qvB1[p] = fmul2(tmp[p], sqk2);
        } else {
            #pragma unroll
            for (int p = 0; p < 4; p++) { qvA1[p] = 0ull; qvB1[p] = 0ull; }
        }
    }

    CP_WAIT0();
    __syncthreads();

    u64 accA0[8], accA1[8], accB0[8], accB1[8];
    #pragma unroll
    for (int p = 0; p < 8; p++) { accA0[p] = 0ull; accA1[p] = 0ull; accB0[p] = 0ull; accB1[p] = 0ull; }

    // per-j body
    auto do_j = [&](int j, const float* kb, const float* vb) {
        u64 k0[4], k1[4];
        ld4(k0, kb + lane * KS);
        ld4(k1, kb + (lane + 32) * KS);

        u64 qeA[4], keA[4], qeB[4], keB[4];
        ld4(qeA, qrel_s + (iA - j + HH - 1) * GC2);
        ld4(keA, krel_s + (j - iA + HH - 1) * GC2);
        ld4(qeB, qrel_s + (iB - j + HH - 1) * GC2);
        ld4(keB, krel_s + (j - iB + HH - 1) * GC2);

        const float LA0 = logit8(qvA0, k0, qeA, keA);
        const float LA1 = logit8(qvA1, k1, qeA, keA);
        const float LB0 = logit8(qvB0, k0, qeB, keB);
        const float LB1 = logit8(qvB1, k1, qeB, keB);

        float PA0, PA1, PB0, PB1;
        softmax2(LA0, LA1, w1ok, PA0, PA1);
        softmax2(LB0, LB1, w1ok, PB0, PB1);

        u64 v0[8], v1[8];
        ld8(v0, vb + lane * VS);
        ld8(v1, vb + (lane + 32) * VS);

        u64 veA[8];
        ld8(veA, vrel_s + (j - iA + HH - 1) * GC);
        const u64 pA0 = pack2(PA0, PA0), pA1 = pack2(PA1, PA1);
        #pragma unroll
        for (int p = 0; p < 8; p++) {
            accA0[p] = ffma2(pA0, fadd2(v0[p], veA[p]), accA0[p]);
            accA1[p] = ffma2(pA1, fadd2(v1[p], veA[p]), accA1[p]);
        }
        u64 veB[8];
        ld8(veB, vrel_s + (j - iB + HH - 1) * GC);
        const u64 pB0 = pack2(PB0, PB0), pB1 = pack2(PB1, PB1);
        #pragma unroll
        for (int p = 0; p < 8; p++) {
            accB0[p] = ffma2(pB0, fadd2(v0[p], veB[p]), accB0[p]);
            accB1[p] = ffma2(pB1, fadd2(v1[p], veB[p]), accB1[p]);
        }
    };

    for (int jj = 0; jj < HH; jj += 2) {
        const int cur = (jj >> 1) & 1, nxt = cur ^ 1;
        if (jj + 2 < HH) { prefetch2(nxt, jj + 2); CP_COMMIT(); }
        do_j(jj,     kbuf[cur],           vbuf[cur]);
        do_j(jj + 1, kbuf[cur] + 64 * KS, vbuf[cur] + 64 * VS);
        CP_WAIT0();
        __syncthreads();
    }

    // ---- epilogue: out = acc*(gsv*BNSCALE) + (bsv+bsve) ----
    {
        u64 s1p[8], bc[8];
        #pragma unroll
        for (int p = 0; p < 8; p++) {
            s1p[p] = pack2(__ldg(gsv + ch0 + 2 * p)     * BNSCALE,
                           __ldg(gsv + ch0 + 2 * p + 1) * BNSCALE);
            bc[p]  = pack2(__ldg(bsv + ch0 + 2 * p)     + __ldg(bsve + ch0 + 2 * p),
                           __ldg(bsv + ch0 + 2 * p + 1) + __ldg(bsve + ch0 + 2 * p + 1));
        }

        const size_t rbA = (((size_t)b * HH + iA) * WW) * OUTC + ch0;
        const size_t rbB = (((size_t)b * HH + iB) * WW) * OUTC + ch0;

        #pragma unroll
        for (int pp = 0; pp < 4; pp++) {
            ulonglong2 o;
            o.x = ffma2(accA0[2 * pp],     s1p[2 * pp],     bc[2 * pp]);
            o.y = ffma2(accA0[2 * pp + 1], s1p[2 * pp + 1], bc[2 * pp + 1]);
            *(ulonglong2*)(out + rbA + (size_t)lane * OUTC + pp * 4) = o;
            o.x = ffma2(accB0[2 * pp],     s1p[2 * pp],     bc[2 * pp]);
            o.y = ffma2(accB0[2 * pp + 1], s1p[2 * pp + 1], bc[2 * pp + 1]);
            *(ulonglong2*)(out + rbB + (size_t)lane * OUTC + pp * 4) = o;
        }
        if (w1ok) {
            #pragma unroll
            for (int pp = 0; pp < 4; pp++) {
                ulonglong2 o;
                o.x = ffma2(accA1[2 * pp],     s1p[2 * pp],     bc[2 * pp]);
                o.y = ffma2(accA1[2 * pp + 1], s1p[2 * pp + 1], bc[2 * pp + 1]);
                *(ulonglong2*)(out + rbA + (size_t)(lane + 32) * OUTC + pp * 4) = o;
                o.x = ffma2(accB1[2 * pp],     s1p[2 * pp],     bc[2 * pp]);
                o.y = ffma2(accB1[2 * pp + 1], s1p[2 * pp + 1], bc[2 * pp + 1]);
                *(ulonglong2*)(out + rbB + (size_t)(lane + 32) * OUTC + pp * 4) = o;
            }
        }
    }
}

// ============================================================
extern "C" void kernel_launch(void* const* d_in, const int* in_sizes, int n_in,
                              void* d_out, int out_size)
{
    const float* x    = (const float*)d_in[0];
    const float* w_q  = (const float*)d_in[1];
    const float* w_k  = (const float*)d_in[2];
    const float* w_v  = (const float*)d_in[3];
    const float* q_rel = (const float*)d_in[4];
    const float* k_rel = (const float*)d_in[5];
    const float* v_rel = (const float*)d_in[6];
    const float* g_q  = (const float*)d_in[7];
    const float* b_q  = (const float*)d_in[8];
    const float* g_k  = (const float*)d_in[9];
    const float* b_k  = (const float*)d_in[10];
    const float* g_v  = (const float*)d_in[11];
    const float* b_v  = (const float*)d_in[12];
    const float* g_qk = (const float*)d_in[13];
    const float* g_qr = (const float*)d_in[15];
    const float* g_kr = (const float*)d_in[17];
    const float* g_sv = (const float*)d_in[19];
    const float* b_sv = (const float*)d_in[20];
    const float* g_sve = (const float*)d_in[21];
    const float* b_sve = (const float*)d_in[22];

    const int proj_smem = (128 * XSP + 128 * 128) * sizeof(float);   // 100352 B
    cudaFuncSetAttribute(proj_kernel, cudaFuncAttributeMaxDynamicSharedMemorySize, proj_smem);

    dim3 g1(2, (NB * HH * WW) / 64);   // (2, 1568)
    proj_kernel<<<g1, 256, proj_smem>>>(x, w_q, w_k, w_v,
                                        g_q, b_q, g_k, b_k, g_v, b_v);

    dim3 g2(7, GRP, NB);               // 8 i-rows per CTA (4 warps × 2)
    attn_kernel<<<g2, 128>>>(q_rel, k_rel, v_rel,
                             g_qk, g_qr, g_kr,
                             g_sv, b_sv, g_sve, b_sve,
                             (float*)d_out);
}